// round 10
// baseline (speedup 1.0000x reference)
#include <cuda_runtime.h>
#include <math.h>

#define S_IN 32
#define V_IN 16
#define S_H  64
#define V_H  32
#define S_OUT 32
#define V_OUT 16
#define NF2_SS 2080
#define NF2    2608
#define RPC 64
#define TPB 256
#define PW1S_C  0.02795084971874737f
#define INV3_C  0.5773502691896258f
#define PW2S  0.0139754248593737f
#define PW2S3 0.0080687153045988f
#define CW1V  0.03125f
#define CW2V  0.015625f

typedef unsigned long long u64;

__device__ __align__(16) float2 g_W1ssR[S_IN * S_IN * S_H];   // raw dup 512KB
__device__ __align__(16) float2 g_W1vvR[V_IN * V_IN * S_H];   // raw dup 128KB
__device__ __align__(16) float2 g_W1v[S_IN * V_IN * V_H];
__device__ __align__(16) float2 g_W2s[NF2 * S_OUT];
__device__ __align__(16) float2 g_W2v[S_H * V_H * V_OUT];

__device__ __forceinline__ u64 f2mul(u64 a, u64 b) {
    u64 r; asm("mul.rn.f32x2 %0,%1,%2;" : "=l"(r) : "l"(a), "l"(b)); return r;
}
__device__ __forceinline__ u64 f2add(u64 a, u64 b) {
    u64 r; asm("add.rn.f32x2 %0,%1,%2;" : "=l"(r) : "l"(a), "l"(b)); return r;
}
__device__ __forceinline__ u64 f2fma(u64 a, u64 b, u64 c) {
    u64 r; asm("fma.rn.f32x2 %0,%1,%2,%3;" : "=l"(r) : "l"(a), "l"(b), "l"(c)); return r;
}
__device__ __forceinline__ float2 unp(u64 v) {
    return make_float2(__uint_as_float((unsigned)v), __uint_as_float((unsigned)(v >> 32)));
}
__device__ __forceinline__ u64 pk(float x, float y) {
    return (u64)__float_as_uint(x) | ((u64)__float_as_uint(y) << 32);
}
// XLA logistic expansion: 0.5 + 0.5*tanh(0.5*x), tanh -> libdevice __nv_tanhf == tanhf
__device__ __forceinline__ float sgp(float a) {
    float t = tanhf(__fmul_rn(a, 0.5f));
    return __fadd_rn(0.5f, __fmul_rn(0.5f, t));
}

#define FMA4(p, wa, wb, A) { (A)[0]=f2fma(p,(wa).x,(A)[0]); (A)[1]=f2fma(p,(wa).y,(A)[1]); \
                             (A)[2]=f2fma(p,(wb).x,(A)[2]); (A)[3]=f2fma(p,(wb).y,(A)[3]); }

// ---- prep ----
__global__ void prep_w1ssR(const float* __restrict__ W) {   // 1024 x 64
    float v = W[blockIdx.x * S_H + threadIdx.x];
    g_W1ssR[blockIdx.x * S_H + threadIdx.x] = make_float2(v, v);
}
__global__ void prep_w1vvR(const float* __restrict__ W) {   // 256 x 64
    float v = W[blockIdx.x * S_H + threadIdx.x];
    g_W1vvR[blockIdx.x * S_H + threadIdx.x] = make_float2(v, v);
}
__global__ void prep_w1v(const float* __restrict__ Wsvv, const float* __restrict__ Wvsv) {
    int u = blockIdx.x, v = blockIdx.y, w = threadIdx.x;    // 32 x 16 x 32
    float val = CW1V * (Wsvv[(u * V_IN + v) * V_H + w] + Wvsv[(v * S_IN + u) * V_H + w]);
    g_W1v[(u * V_IN + v) * V_H + w] = make_float2(val, val);
}
__global__ void prep_w2s_ss(const float* __restrict__ W) {
    int u = blockIdx.x, w = threadIdx.x;                    // 64 x 32
    for (int v = u; v < S_H; ++v) {
        int f = u * S_H - (u * (u - 1)) / 2 + (v - u);
        float val = W[(u * S_H + v) * S_OUT + w];
        if (v > u) val += W[(v * S_H + u) * S_OUT + w];
        val *= PW2S;
        g_W2s[f * S_OUT + w] = make_float2(val, val);
    }
}
__global__ void prep_w2s_vv(const float* __restrict__ W) {
    int u = blockIdx.x, w = threadIdx.x;                    // 32 x 32
    for (int v = u; v < V_H; ++v) {
        int f = NF2_SS + u * V_H - (u * (u - 1)) / 2 + (v - u);
        float val = W[(u * V_H + v) * S_OUT + w];
        if (v > u) val += W[(v * V_H + u) * S_OUT + w];
        val *= PW2S3;
        g_W2s[f * S_OUT + w] = make_float2(val, val);
    }
}
__global__ void prep_w2v(const float* __restrict__ Wsvv, const float* __restrict__ Wvsv) {
    int u = blockIdx.x, v = blockIdx.y, w = threadIdx.x;    // 64 x 32 x 16
    float val = CW2V * (Wsvv[(u * V_H + v) * V_OUT + w] + Wvsv[(v * S_H + u) * V_OUT + w]);
    g_W2v[(u * V_H + v) * V_OUT + w] = make_float2(val, val);
}

// ---- main fused kernel ----
__global__ void __launch_bounds__(TPB, 2)
dl_main(const float* __restrict__ x, const float* __restrict__ b1,
        const float* __restrict__ b3, float* __restrict__ out, int N)
{
    extern __shared__ float sm[];
    float* hs0 = sm;                     // [32][RPC]
    float* hv0 = hs0 + S_IN * RPC;       // [48][RPC]
    float* hs1 = hv0 + 3 * V_IN * RPC;   // [64][RPC]
    float* hv1 = hs1 + S_H * RPC;        // [96][RPC]
    const int tid = threadIdx.x;
    const int row0 = blockIdx.x * RPC;

    // stage 0: load + norm_act(b1, normalize=False), rn ops + tanh-sigmoid
    for (int idx = tid; idx < RPC * 48; idx += TPB) {
        int r = idx / 48, c = idx - r * 48, n = row0 + r;
        if (c < S_IN) {
            float v = (n < N) ? __ldg(x + (size_t)n * 80 + c) : 0.f;
            float m = sgp(__fadd_rn(fabsf(v), __ldg(b1 + c)));
            hs0[c * RPC + r] = __fmul_rn(v, m);
        } else {
            int u = c - S_IN;
            float a = 0.f, b = 0.f, d = 0.f;
            if (n < N) {
                const float* p = x + (size_t)n * 80 + 32 + 3 * u;
                a = __ldg(p); b = __ldg(p + 1); d = __ldg(p + 2);
            }
            float s2 = __fadd_rn(__fadd_rn(__fmul_rn(a, a), __fmul_rn(b, b)), __fmul_rn(d, d));
            float m = sgp(__fadd_rn(sqrtf(s2), __ldg(b1 + 32 + u)));
            hv0[(u * 3 + 0) * RPC + r] = __fmul_rn(a, m);
            hv0[(u * 3 + 1) * RPC + r] = __fmul_rn(b, m);
            hv0[(u * 3 + 2) * RPC + r] = __fmul_rn(d, m);
        }
    }
    __syncthreads();

    // L1 scalar EXACT path: raw weights, per-term products, split chains,
    // final z = PW1S*(A + INV3*B) in rn-fp32.   16 rg x 4 rows, 16 og x (2 passes x 2 outs)
    {
        const int rg = tid & 15, og = tid >> 4, rb = rg * 4;
        #pragma unroll 1
        for (int pass = 0; pass < 2; ++pass) {
            const int wb = og * 4 + pass * 2;
            u64 aA[2][2][2] = {};   // [split][rowpair][out]
            u64 aB[2][2][2] = {};
            // ss: A = sum_{u,v} fl(hs_u*hs_v) * Wsss1[u,v,w]
            for (int u = 0; u < S_IN; ++u) {
                ulonglong2 hu = *(const ulonglong2*)(hs0 + u * RPC + rb);
                {
                    ulonglong2 wd = __ldg((const ulonglong2*)(g_W1ssR + (u * S_IN + u) * S_H + wb));
                    u64 p0 = f2mul(hu.x, hu.x), p1 = f2mul(hu.y, hu.y);
                    int sp = u & 1;
                    aA[sp][0][0] = f2fma(p0, wd.x, aA[sp][0][0]);
                    aA[sp][0][1] = f2fma(p0, wd.y, aA[sp][0][1]);
                    aA[sp][1][0] = f2fma(p1, wd.x, aA[sp][1][0]);
                    aA[sp][1][1] = f2fma(p1, wd.y, aA[sp][1][1]);
                }
                for (int v = u + 1; v < S_IN; ++v) {
                    ulonglong2 hv = *(const ulonglong2*)(hs0 + v * RPC + rb);
                    u64 p0 = f2mul(hu.x, hv.x), p1 = f2mul(hu.y, hv.y);
                    ulonglong2 w1 = __ldg((const ulonglong2*)(g_W1ssR + (u * S_IN + v) * S_H + wb));
                    ulonglong2 w2 = __ldg((const ulonglong2*)(g_W1ssR + (v * S_IN + u) * S_H + wb));
                    int sp = v & 1;
                    aA[sp][0][0] = f2fma(p0, w1.x, aA[sp][0][0]);
                    aA[sp][0][1] = f2fma(p0, w1.y, aA[sp][0][1]);
                    aA[sp][1][0] = f2fma(p1, w1.x, aA[sp][1][0]);
                    aA[sp][1][1] = f2fma(p1, w1.y, aA[sp][1][1]);
                    sp ^= 1;
                    aA[sp][0][0] = f2fma(p0, w2.x, aA[sp][0][0]);
                    aA[sp][0][1] = f2fma(p0, w2.y, aA[sp][0][1]);
                    aA[sp][1][0] = f2fma(p1, w2.x, aA[sp][1][0]);
                    aA[sp][1][1] = f2fma(p1, w2.y, aA[sp][1][1]);
                }
            }
            // vv: B = sum_{u,v} q_uv * Wvvs1[u,v,w],  q = fma chain over i
            for (int u = 0; u < V_IN; ++u) {
                ulonglong2 h0 = *(const ulonglong2*)(hv0 + (u * 3 + 0) * RPC + rb);
                ulonglong2 h1 = *(const ulonglong2*)(hv0 + (u * 3 + 1) * RPC + rb);
                ulonglong2 h2 = *(const ulonglong2*)(hv0 + (u * 3 + 2) * RPC + rb);
                {
                    ulonglong2 wd = __ldg((const ulonglong2*)(g_W1vvR + (u * V_IN + u) * S_H + wb));
                    u64 q0 = f2fma(h2.x, h2.x, f2fma(h1.x, h1.x, f2mul(h0.x, h0.x)));
                    u64 q1 = f2fma(h2.y, h2.y, f2fma(h1.y, h1.y, f2mul(h0.y, h0.y)));
                    int sp = u & 1;
                    aB[sp][0][0] = f2fma(q0, wd.x, aB[sp][0][0]);
                    aB[sp][0][1] = f2fma(q0, wd.y, aB[sp][0][1]);
                    aB[sp][1][0] = f2fma(q1, wd.x, aB[sp][1][0]);
                    aB[sp][1][1] = f2fma(q1, wd.y, aB[sp][1][1]);
                }
                for (int v = u + 1; v < V_IN; ++v) {
                    ulonglong2 g0 = *(const ulonglong2*)(hv0 + (v * 3 + 0) * RPC + rb);
                    ulonglong2 g1 = *(const ulonglong2*)(hv0 + (v * 3 + 1) * RPC + rb);
                    ulonglong2 g2 = *(const ulonglong2*)(hv0 + (v * 3 + 2) * RPC + rb);
                    u64 q0 = f2fma(h2.x, g2.x, f2fma(h1.x, g1.x, f2mul(h0.x, g0.x)));
                    u64 q1 = f2fma(h2.y, g2.y, f2fma(h1.y, g1.y, f2mul(h0.y, g0.y)));
                    ulonglong2 w1 = __ldg((const ulonglong2*)(g_W1vvR + (u * V_IN + v) * S_H + wb));
                    ulonglong2 w2 = __ldg((const ulonglong2*)(g_W1vvR + (v * V_IN + u) * S_H + wb));
                    int sp = v & 1;
                    aB[sp][0][0] = f2fma(q0, w1.x, aB[sp][0][0]);
                    aB[sp][0][1] = f2fma(q0, w1.y, aB[sp][0][1]);
                    aB[sp][1][0] = f2fma(q1, w1.x, aB[sp][1][0]);
                    aB[sp][1][1] = f2fma(q1, w1.y, aB[sp][1][1]);
                    sp ^= 1;
                    aB[sp][0][0] = f2fma(q0, w2.x, aB[sp][0][0]);
                    aB[sp][0][1] = f2fma(q0, w2.y, aB[sp][0][1]);
                    aB[sp][1][0] = f2fma(q1, w2.x, aB[sp][1][0]);
                    aB[sp][1][1] = f2fma(q1, w2.y, aB[sp][1][1]);
                }
            }
            // finalize: ref op order, rn-fp32
            #pragma unroll
            for (int rp = 0; rp < 2; ++rp)
                #pragma unroll
                for (int o = 0; o < 2; ++o) {
                    float2 A = unp(f2add(aA[0][rp][o], aA[1][rp][o]));
                    float2 B = unp(f2add(aB[0][rp][o], aB[1][rp][o]));
                    float zx = __fmul_rn(PW1S_C, __fadd_rn(A.x, __fmul_rn(INV3_C, B.x)));
                    float zy = __fmul_rn(PW1S_C, __fadd_rn(A.y, __fmul_rn(INV3_C, B.y)));
                    float hx = copysignf(sgp(fabsf(zx)), zx);
                    float hy = copysignf(sgp(fabsf(zy)), zy);
                    *(u64*)(hs1 + (wb + o) * RPC + rb + 2 * rp) = pk(hx, hy);
                }
        }
    }

    // L1 vector (continuous): R3 fast path
    {
        const int rg = tid & 31, og = tid >> 5, rb = rg * 2;
        const float2* Wb = g_W1v + og * 4;
        u64 acc[3][4] = {};
        for (int v = 0; v < V_IN; ++v) {
            u64 hv[3];
            #pragma unroll
            for (int k = 0; k < 3; ++k) hv[k] = *(const u64*)(hv0 + (v * 3 + k) * RPC + rb);
            for (int u = 0; u < S_IN; ++u) {
                const ulonglong2* wp = (const ulonglong2*)(Wb + (u * V_IN + v) * V_H);
                ulonglong2 wa = __ldg(wp), wb2 = __ldg(wp + 1);
                u64 hu = *(const u64*)(hs0 + u * RPC + rb);
                #pragma unroll
                for (int k = 0; k < 3; ++k) {
                    u64 p = f2mul(hu, hv[k]);
                    FMA4(p, wa, wb2, acc[k]);
                }
            }
        }
        #pragma unroll
        for (int wi = 0; wi < 4; ++wi) {
            int w = og * 4 + wi;
            float2 a0 = unp(acc[0][wi]), a1 = unp(acc[1][wi]), a2 = unp(acc[2][wi]);
            float nx = sqrtf(a0.x * a0.x + a1.x * a1.x + a2.x * a2.x);
            float ny = sqrtf(a0.y * a0.y + a1.y * a1.y + a2.y * a2.y);
            float mx = sgp(nx) / nx, my = sgp(ny) / ny;
            *(u64*)(hv1 + (w * 3 + 0) * RPC + rb) = pk(a0.x * mx, a0.y * my);
            *(u64*)(hv1 + (w * 3 + 1) * RPC + rb) = pk(a1.x * mx, a1.y * my);
            *(u64*)(hv1 + (w * 3 + 2) * RPC + rb) = pk(a2.x * mx, a2.y * my);
        }
    }
    __syncthreads();

    // L2 scalar (continuous): R3 fast path
    {
        const int rg = tid & 31, og = tid >> 5, rb = rg * 2;
        const float2* Wb = g_W2s + og * 4;
        u64 acc[4] = {};
        int f = 0;
        for (int u = 0; u < S_H; ++u) {
            u64 hu = *(const u64*)(hs1 + u * RPC + rb);
            for (int v = u; v < S_H; ++v, ++f) {
                const ulonglong2* wp = (const ulonglong2*)(Wb + f * S_OUT);
                ulonglong2 wa = __ldg(wp), wb2 = __ldg(wp + 1);
                u64 hv = *(const u64*)(hs1 + v * RPC + rb);
                u64 p = f2mul(hu, hv);
                FMA4(p, wa, wb2, acc);
            }
        }
        for (int u = 0; u < V_H; ++u) {
            u64 h0 = *(const u64*)(hv1 + (u * 3 + 0) * RPC + rb);
            u64 h1 = *(const u64*)(hv1 + (u * 3 + 1) * RPC + rb);
            u64 h2 = *(const u64*)(hv1 + (u * 3 + 2) * RPC + rb);
            for (int v = u; v < V_H; ++v, ++f) {
                const ulonglong2* wp = (const ulonglong2*)(Wb + f * S_OUT);
                ulonglong2 wa = __ldg(wp), wb2 = __ldg(wp + 1);
                u64 g0 = *(const u64*)(hv1 + (v * 3 + 0) * RPC + rb);
                u64 g1 = *(const u64*)(hv1 + (v * 3 + 1) * RPC + rb);
                u64 g2 = *(const u64*)(hv1 + (v * 3 + 2) * RPC + rb);
                u64 p = f2mul(h0, g0); p = f2fma(h1, g1, p); p = f2fma(h2, g2, p);
                FMA4(p, wa, wb2, acc);
            }
        }
        int n0 = row0 + rb, n1 = n0 + 1;
        #pragma unroll
        for (int wi = 0; wi < 4; ++wi) {
            int w = og * 4 + wi;
            float bw = __ldg(b3 + w);
            float2 z = unp(acc[wi]);
            if (n0 < N) out[(size_t)n0 * 80 + w] = z.x * sgp(fabsf(z.x) + bw);
            if (n1 < N) out[(size_t)n1 * 80 + w] = z.y * sgp(fabsf(z.y) + bw);
        }
    }

    // L2 vector (continuous): R3 fast path
    {
        const int rg = tid & 31, og = tid >> 5, rb = rg * 2;
        const float2* Wb = g_W2v + og * 2;
        u64 acc[3][2] = {};
        for (int v = 0; v < V_H; ++v) {
            u64 hv[3];
            #pragma unroll
            for (int k = 0; k < 3; ++k) hv[k] = *(const u64*)(hv1 + (v * 3 + k) * RPC + rb);
            for (int u = 0; u < S_H; ++u) {
                ulonglong2 wv = __ldg((const ulonglong2*)(Wb + (u * V_H + v) * V_OUT));
                u64 hu = *(const u64*)(hs1 + u * RPC + rb);
                #pragma unroll
                for (int k = 0; k < 3; ++k) {
                    u64 p = f2mul(hu, hv[k]);
                    acc[k][0] = f2fma(p, wv.x, acc[k][0]);
                    acc[k][1] = f2fma(p, wv.y, acc[k][1]);
                }
            }
        }
        int n0 = row0 + rb, n1 = n0 + 1;
        #pragma unroll
        for (int wi = 0; wi < 2; ++wi) {
            int w = og * 2 + wi;
            float bw = __ldg(b3 + 32 + w);
            float2 a0 = unp(acc[0][wi]), a1 = unp(acc[1][wi]), a2 = unp(acc[2][wi]);
            float mx = sgp(sqrtf(a0.x * a0.x + a1.x * a1.x + a2.x * a2.x) + bw);
            float my = sgp(sqrtf(a0.y * a0.y + a1.y * a1.y + a2.y * a2.y) + bw);
            if (n0 < N) {
                float* o = out + (size_t)n0 * 80 + 32 + 3 * w;
                o[0] = a0.x * mx; o[1] = a1.x * mx; o[2] = a2.x * mx;
            }
            if (n1 < N) {
                float* o = out + (size_t)n1 * 80 + 32 + 3 * w;
                o[0] = a0.y * my; o[1] = a1.y * my; o[2] = a2.y * my;
            }
        }
    }
}

extern "C" void kernel_launch(void* const* d_in, const int* in_sizes, int n_in,
                              void* d_out, int out_size) {
    const float* x     = (const float*)d_in[0];
    const float* Wsss1 = (const float*)d_in[1];
    const float* Wvvs1 = (const float*)d_in[2];
    const float* Wsvv1 = (const float*)d_in[3];
    const float* Wvsv1 = (const float*)d_in[4];
    const float* Wsss2 = (const float*)d_in[5];
    const float* Wvvs2 = (const float*)d_in[6];
    const float* Wsvv2 = (const float*)d_in[7];
    const float* Wvsv2 = (const float*)d_in[8];
    const float* b1    = (const float*)d_in[9];
    const float* b3    = (const float*)d_in[10];
    float* out = (float*)d_out;
    int N = in_sizes[0] / 80;

    prep_w1ssR<<<S_IN * S_IN, S_H>>>(Wsss1);
    prep_w1vvR<<<V_IN * V_IN, S_H>>>(Wvvs1);
    prep_w1v<<<dim3(S_IN, V_IN), V_H>>>(Wsvv1, Wvsv1);
    prep_w2s_ss<<<S_H, S_OUT>>>(Wsss2);
    prep_w2s_vv<<<V_H, S_OUT>>>(Wvvs2);
    prep_w2v<<<dim3(S_H, V_H), V_OUT>>>(Wsvv2, Wvsv2);

    const int smem = 240 * RPC * sizeof(float);  // 61440 B
    cudaFuncSetAttribute(dl_main, cudaFuncAttributeMaxDynamicSharedMemorySize, smem);
    int blocks = (N + RPC - 1) / RPC;
    dl_main<<<blocks, TPB, smem>>>(x, b1, b3, out, N);
}

// round 11
// speedup vs baseline: 1.2417x; 1.2417x over previous
#include <cuda_runtime.h>
#include <math.h>

#define S_IN 32
#define V_IN 16
#define S_H  64
#define V_H  32
#define S_OUT 32
#define V_OUT 16
#define NF2_SS 2080
#define NF2    2608
#define RPC 64
#define TPB 256
#define PW1S_C  0.02795084971874737f
#define INV3_C  0.5773502691896258f
#define PW2S  0.0139754248593737f
#define PW2S3 0.0080687153045988f
#define CW1V  0.03125f
#define CW2V  0.015625f

typedef unsigned long long u64;

__device__ __align__(16) float2 g_W1ssR[S_IN * S_IN * S_H];
__device__ __align__(16) float2 g_W1vvR[V_IN * V_IN * S_H];
__device__ __align__(16) float2 g_W1v[S_IN * V_IN * V_H];
__device__ __align__(16) float2 g_W2s[NF2 * S_OUT];
__device__ __align__(16) float2 g_W2v[S_H * V_H * V_OUT];

__device__ __forceinline__ u64 f2mul(u64 a, u64 b) {
    u64 r; asm("mul.rn.f32x2 %0,%1,%2;" : "=l"(r) : "l"(a), "l"(b)); return r;
}
__device__ __forceinline__ u64 f2add(u64 a, u64 b) {
    u64 r; asm("add.rn.f32x2 %0,%1,%2;" : "=l"(r) : "l"(a), "l"(b)); return r;
}
__device__ __forceinline__ u64 f2fma(u64 a, u64 b, u64 c) {
    u64 r; asm("fma.rn.f32x2 %0,%1,%2,%3;" : "=l"(r) : "l"(a), "l"(b), "l"(c)); return r;
}
__device__ __forceinline__ float2 unp(u64 v) {
    return make_float2(__uint_as_float((unsigned)v), __uint_as_float((unsigned)(v >> 32)));
}
__device__ __forceinline__ u64 pk(float x, float y) {
    return (u64)__float_as_uint(x) | ((u64)__float_as_uint(y) << 32);
}
// XLA logistic expansion: 0.5 + 0.5*tanh(0.5*x)
__device__ __forceinline__ float sgp(float a) {
    float t = tanhf(__fmul_rn(a, 0.5f));
    return __fadd_rn(0.5f, __fmul_rn(0.5f, t));
}

#define FMA4(p, wa, wb, A) { (A)[0]=f2fma(p,(wa).x,(A)[0]); (A)[1]=f2fma(p,(wa).y,(A)[1]); \
                             (A)[2]=f2fma(p,(wb).x,(A)[2]); (A)[3]=f2fma(p,(wb).y,(A)[3]); }

// ---- single fused prep kernel: 294912 items = 1152 blocks x 256 ----
__global__ void prep_all(const float* __restrict__ Wsss1, const float* __restrict__ Wvvs1,
                         const float* __restrict__ Wsvv1, const float* __restrict__ Wvsv1,
                         const float* __restrict__ Wsss2, const float* __restrict__ Wvvs2,
                         const float* __restrict__ Wsvv2, const float* __restrict__ Wvsv2)
{
    int i = blockIdx.x * blockDim.x + threadIdx.x;
    if (i < 65536) {                                  // w1ss raw dup
        float v = Wsss1[i]; g_W1ssR[i] = make_float2(v, v); return;
    }
    i -= 65536;
    if (i < 16384) {                                  // w1vv raw dup
        float v = Wvvs1[i]; g_W1vvR[i] = make_float2(v, v); return;
    }
    i -= 16384;
    if (i < S_IN * V_IN * V_H) {                      // w1v fused (16384)
        int w = i & 31, uv = i >> 5, u = uv / V_IN, v = uv - u * V_IN;
        float val = CW1V * (Wsvv1[(u * V_IN + v) * V_H + w] + Wvsv1[(v * S_IN + u) * V_H + w]);
        g_W1v[i] = make_float2(val, val); return;
    }
    i -= S_IN * V_IN * V_H;
    if (i < 64 * 64 * 32) {                           // w2s_ss folded (131072, half skipped)
        int w = i & 31, uv = i >> 5, u = uv >> 6, v = uv & 63;
        if (v >= u) {
            int f = u * S_H - (u * (u - 1)) / 2 + (v - u);
            float val = Wsss2[(u * S_H + v) * S_OUT + w];
            if (v > u) val += Wsss2[(v * S_H + u) * S_OUT + w];
            val *= PW2S;
            g_W2s[f * S_OUT + w] = make_float2(val, val);
        }
        return;
    }
    i -= 64 * 64 * 32;
    if (i < 32 * 32 * 32) {                           // w2s_vv folded (32768, half skipped)
        int w = i & 31, uv = i >> 5, u = uv >> 5, v = uv & 31;
        if (v >= u) {
            int f = NF2_SS + u * V_H - (u * (u - 1)) / 2 + (v - u);
            float val = Wvvs2[(u * V_H + v) * S_OUT + w];
            if (v > u) val += Wvvs2[(v * V_H + u) * S_OUT + w];
            val *= PW2S3;
            g_W2s[f * S_OUT + w] = make_float2(val, val);
        }
        return;
    }
    i -= 32 * 32 * 32;
    if (i < S_H * V_H * V_OUT) {                      // w2v fused (32768)
        int w = i & 15, uv = i >> 4, u = uv / V_H, v = uv - u * V_H;
        float val = CW2V * (Wsvv2[(u * V_H + v) * V_OUT + w] + Wvsv2[(v * S_H + u) * V_OUT + w]);
        g_W2v[i] = make_float2(val, val); return;
    }
}

// ---- main fused kernel (numerics identical to R10-pass) ----
__global__ void __launch_bounds__(TPB, 3)
dl_main(const float* __restrict__ x, const float* __restrict__ b1,
        const float* __restrict__ b3, float* __restrict__ out, int N)
{
    extern __shared__ float sm[];
    float* hs0 = sm;                     // [32][RPC]
    float* hv0 = hs0 + S_IN * RPC;       // [48][RPC]
    float* hs1 = hv0 + 3 * V_IN * RPC;   // [64][RPC]
    float* hv1 = hs1 + S_H * RPC;        // [96][RPC]
    const int tid = threadIdx.x;
    const int row0 = blockIdx.x * RPC;

    // stage 0: load + norm_act(b1, normalize=False)
    for (int idx = tid; idx < RPC * 48; idx += TPB) {
        int r = idx / 48, c = idx - r * 48, n = row0 + r;
        if (c < S_IN) {
            float v = (n < N) ? __ldg(x + (size_t)n * 80 + c) : 0.f;
            float m = sgp(__fadd_rn(fabsf(v), __ldg(b1 + c)));
            hs0[c * RPC + r] = __fmul_rn(v, m);
        } else {
            int u = c - S_IN;
            float a = 0.f, b = 0.f, d = 0.f;
            if (n < N) {
                const float* p = x + (size_t)n * 80 + 32 + 3 * u;
                a = __ldg(p); b = __ldg(p + 1); d = __ldg(p + 2);
            }
            float s2 = __fadd_rn(__fadd_rn(__fmul_rn(a, a), __fmul_rn(b, b)), __fmul_rn(d, d));
            float m = sgp(__fadd_rn(sqrtf(s2), __ldg(b1 + 32 + u)));
            hv0[(u * 3 + 0) * RPC + r] = __fmul_rn(a, m);
            hv0[(u * 3 + 1) * RPC + r] = __fmul_rn(b, m);
            hv0[(u * 3 + 2) * RPC + r] = __fmul_rn(d, m);
        }
    }
    __syncthreads();

    // L1 scalar EXACT path (split chains, raw weights)
    {
        const int rg = tid & 15, og = tid >> 4, rb = rg * 4;
        #pragma unroll 1
        for (int pass = 0; pass < 2; ++pass) {
            const int wb = og * 4 + pass * 2;
            u64 aA[2][2][2] = {};
            u64 aB[2][2][2] = {};
            for (int u = 0; u < S_IN; ++u) {
                ulonglong2 hu = *(const ulonglong2*)(hs0 + u * RPC + rb);
                {
                    ulonglong2 wd = __ldg((const ulonglong2*)(g_W1ssR + (u * S_IN + u) * S_H + wb));
                    u64 p0 = f2mul(hu.x, hu.x), p1 = f2mul(hu.y, hu.y);
                    int sp = u & 1;
                    aA[sp][0][0] = f2fma(p0, wd.x, aA[sp][0][0]);
                    aA[sp][0][1] = f2fma(p0, wd.y, aA[sp][0][1]);
                    aA[sp][1][0] = f2fma(p1, wd.x, aA[sp][1][0]);
                    aA[sp][1][1] = f2fma(p1, wd.y, aA[sp][1][1]);
                }
                #pragma unroll 4
                for (int v = u + 1; v < S_IN; ++v) {
                    ulonglong2 hv = *(const ulonglong2*)(hs0 + v * RPC + rb);
                    u64 p0 = f2mul(hu.x, hv.x), p1 = f2mul(hu.y, hv.y);
                    ulonglong2 w1 = __ldg((const ulonglong2*)(g_W1ssR + (u * S_IN + v) * S_H + wb));
                    ulonglong2 w2 = __ldg((const ulonglong2*)(g_W1ssR + (v * S_IN + u) * S_H + wb));
                    int sp = v & 1;
                    aA[sp][0][0] = f2fma(p0, w1.x, aA[sp][0][0]);
                    aA[sp][0][1] = f2fma(p0, w1.y, aA[sp][0][1]);
                    aA[sp][1][0] = f2fma(p1, w1.x, aA[sp][1][0]);
                    aA[sp][1][1] = f2fma(p1, w1.y, aA[sp][1][1]);
                    sp ^= 1;
                    aA[sp][0][0] = f2fma(p0, w2.x, aA[sp][0][0]);
                    aA[sp][0][1] = f2fma(p0, w2.y, aA[sp][0][1]);
                    aA[sp][1][0] = f2fma(p1, w2.x, aA[sp][1][0]);
                    aA[sp][1][1] = f2fma(p1, w2.y, aA[sp][1][1]);
                }
            }
            for (int u = 0; u < V_IN; ++u) {
                ulonglong2 h0 = *(const ulonglong2*)(hv0 + (u * 3 + 0) * RPC + rb);
                ulonglong2 h1 = *(const ulonglong2*)(hv0 + (u * 3 + 1) * RPC + rb);
                ulonglong2 h2 = *(const ulonglong2*)(hv0 + (u * 3 + 2) * RPC + rb);
                {
                    ulonglong2 wd = __ldg((const ulonglong2*)(g_W1vvR + (u * V_IN + u) * S_H + wb));
                    u64 q0 = f2fma(h2.x, h2.x, f2fma(h1.x, h1.x, f2mul(h0.x, h0.x)));
                    u64 q1 = f2fma(h2.y, h2.y, f2fma(h1.y, h1.y, f2mul(h0.y, h0.y)));
                    int sp = u & 1;
                    aB[sp][0][0] = f2fma(q0, wd.x, aB[sp][0][0]);
                    aB[sp][0][1] = f2fma(q0, wd.y, aB[sp][0][1]);
                    aB[sp][1][0] = f2fma(q1, wd.x, aB[sp][1][0]);
                    aB[sp][1][1] = f2fma(q1, wd.y, aB[sp][1][1]);
                }
                #pragma unroll 3
                for (int v = u + 1; v < V_IN; ++v) {
                    ulonglong2 g0 = *(const ulonglong2*)(hv0 + (v * 3 + 0) * RPC + rb);
                    ulonglong2 g1 = *(const ulonglong2*)(hv0 + (v * 3 + 1) * RPC + rb);
                    ulonglong2 g2 = *(const ulonglong2*)(hv0 + (v * 3 + 2) * RPC + rb);
                    u64 q0 = f2fma(h2.x, g2.x, f2fma(h1.x, g1.x, f2mul(h0.x, g0.x)));
                    u64 q1 = f2fma(h2.y, g2.y, f2fma(h1.y, g1.y, f2mul(h0.y, g0.y)));
                    ulonglong2 w1 = __ldg((const ulonglong2*)(g_W1vvR + (u * V_IN + v) * S_H + wb));
                    ulonglong2 w2 = __ldg((const ulonglong2*)(g_W1vvR + (v * V_IN + u) * S_H + wb));
                    int sp = v & 1;
                    aB[sp][0][0] = f2fma(q0, w1.x, aB[sp][0][0]);
                    aB[sp][0][1] = f2fma(q0, w1.y, aB[sp][0][1]);
                    aB[sp][1][0] = f2fma(q1, w1.x, aB[sp][1][0]);
                    aB[sp][1][1] = f2fma(q1, w1.y, aB[sp][1][1]);
                    sp ^= 1;
                    aB[sp][0][0] = f2fma(q0, w2.x, aB[sp][0][0]);
                    aB[sp][0][1] = f2fma(q0, w2.y, aB[sp][0][1]);
                    aB[sp][1][0] = f2fma(q1, w2.x, aB[sp][1][0]);
                    aB[sp][1][1] = f2fma(q1, w2.y, aB[sp][1][1]);
                }
            }
            #pragma unroll
            for (int rp = 0; rp < 2; ++rp)
                #pragma unroll
                for (int o = 0; o < 2; ++o) {
                    float2 A = unp(f2add(aA[0][rp][o], aA[1][rp][o]));
                    float2 B = unp(f2add(aB[0][rp][o], aB[1][rp][o]));
                    float zx = __fmul_rn(PW1S_C, __fadd_rn(A.x, __fmul_rn(INV3_C, B.x)));
                    float zy = __fmul_rn(PW1S_C, __fadd_rn(A.y, __fmul_rn(INV3_C, B.y)));
                    float hx = copysignf(sgp(fabsf(zx)), zx);
                    float hy = copysignf(sgp(fabsf(zy)), zy);
                    *(u64*)(hs1 + (wb + o) * RPC + rb + 2 * rp) = pk(hx, hy);
                }
        }
    }

    // L1 vector
    {
        const int rg = tid & 31, og = tid >> 5, rb = rg * 2;
        const float2* Wb = g_W1v + og * 4;
        u64 acc[3][4] = {};
        for (int v = 0; v < V_IN; ++v) {
            u64 hv[3];
            #pragma unroll
            for (int k = 0; k < 3; ++k) hv[k] = *(const u64*)(hv0 + (v * 3 + k) * RPC + rb);
            #pragma unroll 4
            for (int u = 0; u < S_IN; ++u) {
                const ulonglong2* wp = (const ulonglong2*)(Wb + (u * V_IN + v) * V_H);
                ulonglong2 wa = __ldg(wp), wb2 = __ldg(wp + 1);
                u64 hu = *(const u64*)(hs0 + u * RPC + rb);
                #pragma unroll
                for (int k = 0; k < 3; ++k) {
                    u64 p = f2mul(hu, hv[k]);
                    FMA4(p, wa, wb2, acc[k]);
                }
            }
        }
        #pragma unroll
        for (int wi = 0; wi < 4; ++wi) {
            int w = og * 4 + wi;
            float2 a0 = unp(acc[0][wi]), a1 = unp(acc[1][wi]), a2 = unp(acc[2][wi]);
            float nx = sqrtf(a0.x * a0.x + a1.x * a1.x + a2.x * a2.x);
            float ny = sqrtf(a0.y * a0.y + a1.y * a1.y + a2.y * a2.y);
            float mx = sgp(nx) / nx, my = sgp(ny) / ny;
            *(u64*)(hv1 + (w * 3 + 0) * RPC + rb) = pk(a0.x * mx, a0.y * my);
            *(u64*)(hv1 + (w * 3 + 1) * RPC + rb) = pk(a1.x * mx, a1.y * my);
            *(u64*)(hv1 + (w * 3 + 2) * RPC + rb) = pk(a2.x * mx, a2.y * my);
        }
    }
    __syncthreads();

    // L2 scalar
    {
        const int rg = tid & 31, og = tid >> 5, rb = rg * 2;
        const float2* Wb = g_W2s + og * 4;
        u64 acc[4] = {};
        int f = 0;
        for (int u = 0; u < S_H; ++u) {
            u64 hu = *(const u64*)(hs1 + u * RPC + rb);
            #pragma unroll 4
            for (int v = u; v < S_H; ++v, ++f) {
                const ulonglong2* wp = (const ulonglong2*)(Wb + f * S_OUT);
                ulonglong2 wa = __ldg(wp), wb2 = __ldg(wp + 1);
                u64 hv = *(const u64*)(hs1 + v * RPC + rb);
                u64 p = f2mul(hu, hv);
                FMA4(p, wa, wb2, acc);
            }
        }
        for (int u = 0; u < V_H; ++u) {
            u64 h0 = *(const u64*)(hv1 + (u * 3 + 0) * RPC + rb);
            u64 h1 = *(const u64*)(hv1 + (u * 3 + 1) * RPC + rb);
            u64 h2 = *(const u64*)(hv1 + (u * 3 + 2) * RPC + rb);
            #pragma unroll 4
            for (int v = u; v < V_H; ++v, ++f) {
                const ulonglong2* wp = (const ulonglong2*)(Wb + f * S_OUT);
                ulonglong2 wa = __ldg(wp), wb2 = __ldg(wp + 1);
                u64 g0 = *(const u64*)(hv1 + (v * 3 + 0) * RPC + rb);
                u64 g1 = *(const u64*)(hv1 + (v * 3 + 1) * RPC + rb);
                u64 g2 = *(const u64*)(hv1 + (v * 3 + 2) * RPC + rb);
                u64 p = f2mul(h0, g0); p = f2fma(h1, g1, p); p = f2fma(h2, g2, p);
                FMA4(p, wa, wb2, acc);
            }
        }
        int n0 = row0 + rb, n1 = n0 + 1;
        #pragma unroll
        for (int wi = 0; wi < 4; ++wi) {
            int w = og * 4 + wi;
            float bw = __ldg(b3 + w);
            float2 z = unp(acc[wi]);
            if (n0 < N) out[(size_t)n0 * 80 + w] = z.x * sgp(fabsf(z.x) + bw);
            if (n1 < N) out[(size_t)n1 * 80 + w] = z.y * sgp(fabsf(z.y) + bw);
        }
    }

    // L2 vector
    {
        const int rg = tid & 31, og = tid >> 5, rb = rg * 2;
        const float2* Wb = g_W2v + og * 2;
        u64 acc[3][2] = {};
        for (int v = 0; v < V_H; ++v) {
            u64 hv[3];
            #pragma unroll
            for (int k = 0; k < 3; ++k) hv[k] = *(const u64*)(hv1 + (v * 3 + k) * RPC + rb);
            #pragma unroll 4
            for (int u = 0; u < S_H; ++u) {
                ulonglong2 wv = __ldg((const ulonglong2*)(Wb + (u * V_H + v) * V_OUT));
                u64 hu = *(const u64*)(hs1 + u * RPC + rb);
                #pragma unroll
                for (int k = 0; k < 3; ++k) {
                    u64 p = f2mul(hu, hv[k]);
                    acc[k][0] = f2fma(p, wv.x, acc[k][0]);
                    acc[k][1] = f2fma(p, wv.y, acc[k][1]);
                }
            }
        }
        int n0 = row0 + rb, n1 = n0 + 1;
        #pragma unroll
        for (int wi = 0; wi < 2; ++wi) {
            int w = og * 2 + wi;
            float bw = __ldg(b3 + 32 + w);
            float2 a0 = unp(acc[0][wi]), a1 = unp(acc[1][wi]), a2 = unp(acc[2][wi]);
            float mx = sgp(sqrtf(a0.x * a0.x + a1.x * a1.x + a2.x * a2.x) + bw);
            float my = sgp(sqrtf(a0.y * a0.y + a1.y * a1.y + a2.y * a2.y) + bw);
            if (n0 < N) {
                float* o = out + (size_t)n0 * 80 + 32 + 3 * w;
                o[0] = a0.x * mx; o[1] = a1.x * mx; o[2] = a2.x * mx;
            }
            if (n1 < N) {
                float* o = out + (size_t)n1 * 80 + 32 + 3 * w;
                o[0] = a0.y * my; o[1] = a1.y * my; o[2] = a2.y * my;
            }
        }
    }
}

extern "C" void kernel_launch(void* const* d_in, const int* in_sizes, int n_in,
                              void* d_out, int out_size) {
    const float* x     = (const float*)d_in[0];
    const float* Wsss1 = (const float*)d_in[1];
    const float* Wvvs1 = (const float*)d_in[2];
    const float* Wsvv1 = (const float*)d_in[3];
    const float* Wvsv1 = (const float*)d_in[4];
    const float* Wsss2 = (const float*)d_in[5];
    const float* Wvvs2 = (const float*)d_in[6];
    const float* Wsvv2 = (const float*)d_in[7];
    const float* Wvsv2 = (const float*)d_in[8];
    const float* b1    = (const float*)d_in[9];
    const float* b3    = (const float*)d_in[10];
    float* out = (float*)d_out;
    int N = in_sizes[0] / 80;

    prep_all<<<1152, 256>>>(Wsss1, Wvvs1, Wsvv1, Wvsv1, Wsss2, Wvvs2, Wsvv2, Wvsv2);

    const int smem = 240 * RPC * sizeof(float);  // 61440 B
    cudaFuncSetAttribute(dl_main, cudaFuncAttributeMaxDynamicSharedMemorySize, smem);
    int blocks = (N + RPC - 1) / RPC;
    dl_main<<<blocks, TPB, smem>>>(x, b1, b3, out, N);
}

// round 13
// speedup vs baseline: 1.2747x; 1.0266x over previous
#include <cuda_runtime.h>
#include <math.h>

#define S_IN 32
#define V_IN 16
#define S_H  64
#define V_H  32
#define S_OUT 32
#define V_OUT 16
#define NF2_SS 2080
#define NF2    2608
#define RPC 64
#define TPB 256
#define PW1S_C  0.02795084971874737f
#define INV3_C  0.5773502691896258f
#define PW2S  0.0139754248593737f
#define PW2S3 0.0080687153045988f
#define CW1V  0.03125f
#define CW2V  0.015625f

typedef unsigned long long u64;

__device__ __align__(16) float  g_W1v[S_IN * V_IN * V_H];   // raw, scaled
__device__ __align__(16) float  g_W2s[NF2 * S_OUT];         // raw, folded+scaled
__device__ __align__(16) float2 g_W2v[S_H * V_H * V_OUT];   // dup, fused+scaled

__device__ __forceinline__ u64 f2mul(u64 a, u64 b) {
    u64 r; asm("mul.rn.f32x2 %0,%1,%2;" : "=l"(r) : "l"(a), "l"(b)); return r;
}
__device__ __forceinline__ u64 f2add(u64 a, u64 b) {
    u64 r; asm("add.rn.f32x2 %0,%1,%2;" : "=l"(r) : "l"(a), "l"(b)); return r;
}
__device__ __forceinline__ u64 f2fma(u64 a, u64 b, u64 c) {
    u64 r; asm("fma.rn.f32x2 %0,%1,%2,%3;" : "=l"(r) : "l"(a), "l"(b), "l"(c)); return r;
}
__device__ __forceinline__ float2 unp(u64 v) {
    return make_float2(__uint_as_float((unsigned)v), __uint_as_float((unsigned)(v >> 32)));
}
__device__ __forceinline__ u64 pk(float x, float y) {
    return (u64)__float_as_uint(x) | ((u64)__float_as_uint(y) << 32);
}
__device__ __forceinline__ u64 dupf(float w) {
    u64 b = (u64)__float_as_uint(w); return b | (b << 32);
}
// XLA logistic: 0.5 + 0.5*tanh(0.5*x)
__device__ __forceinline__ float sgp(float a) {
    float t = tanhf(__fmul_rn(a, 0.5f));
    return __fadd_rn(0.5f, __fmul_rn(0.5f, t));
}

#define DUP4(d, W_) u64 d[4] = {dupf((W_).x), dupf((W_).y), dupf((W_).z), dupf((W_).w)}

// ---- fused prep: 212992 items = 832 x 256 ----
__global__ void prep_all(const float* __restrict__ Wsvv1, const float* __restrict__ Wvsv1,
                         const float* __restrict__ Wsss2, const float* __restrict__ Wvvs2,
                         const float* __restrict__ Wsvv2, const float* __restrict__ Wvsv2)
{
    int i = blockIdx.x * blockDim.x + threadIdx.x;
    if (i < 16384) {                                  // w1v raw fused
        int w = i & 31, uv = i >> 5, u = uv >> 4, v = uv & 15;
        g_W1v[i] = CW1V * (Wsvv1[(u * V_IN + v) * V_H + w] + Wvsv1[(v * S_IN + u) * V_H + w]);
        return;
    }
    i -= 16384;
    if (i < 131072) {                                 // w2s ss folded raw
        int w = i & 31, uv = i >> 5, u = uv >> 6, v = uv & 63;
        if (v >= u) {
            int f = u * S_H - (u * (u - 1)) / 2 + (v - u);
            float val = Wsss2[(u * S_H + v) * S_OUT + w];
            if (v > u) val += Wsss2[(v * S_H + u) * S_OUT + w];
            g_W2s[f * S_OUT + w] = val * PW2S;
        }
        return;
    }
    i -= 131072;
    if (i < 32768) {                                  // w2s vv folded raw
        int w = i & 31, uv = i >> 5, u = uv >> 5, v = uv & 31;
        if (v >= u) {
            int f = NF2_SS + u * V_H - (u * (u - 1)) / 2 + (v - u);
            float val = Wvvs2[(u * V_H + v) * S_OUT + w];
            if (v > u) val += Wvvs2[(v * V_H + u) * S_OUT + w];
            g_W2s[f * S_OUT + w] = val * PW2S3;
        }
        return;
    }
    i -= 32768;
    if (i < 32768) {                                  // w2v dup fused
        int w = i & 15, uv = i >> 4, u = uv >> 5, v = uv & 31;
        float val = CW2V * (Wsvv2[(u * V_H + v) * V_OUT + w] + Wvsv2[(v * S_H + u) * V_OUT + w]);
        g_W2v[i] = make_float2(val, val);
    }
}

// ---- main fused kernel (bit-identical numerics to R11-pass) ----
__global__ void __launch_bounds__(TPB, 2)
dl_main(const float* __restrict__ x,
        const float* __restrict__ Wsss1, const float* __restrict__ Wvvs1,
        const float* __restrict__ b1, const float* __restrict__ b3,
        float* __restrict__ out, int N)
{
    extern __shared__ float sm[];
    float* hs0 = sm;                     // [32][RPC]
    float* hv0 = hs0 + S_IN * RPC;       // [48][RPC]
    float* hs1 = hv0 + 3 * V_IN * RPC;   // [64][RPC]
    float* hv1 = hs1 + S_H * RPC;        // [96][RPC]
    const int tid = threadIdx.x;
    const int row0 = blockIdx.x * RPC;

    // stage 0
    for (int idx = tid; idx < RPC * 48; idx += TPB) {
        int r = idx / 48, c = idx - r * 48, n = row0 + r;
        if (c < S_IN) {
            float v = (n < N) ? __ldg(x + (size_t)n * 80 + c) : 0.f;
            float m = sgp(__fadd_rn(fabsf(v), __ldg(b1 + c)));
            hs0[c * RPC + r] = __fmul_rn(v, m);
        } else {
            int u = c - S_IN;
            float a = 0.f, b = 0.f, d = 0.f;
            if (n < N) {
                const float* p = x + (size_t)n * 80 + 32 + 3 * u;
                a = __ldg(p); b = __ldg(p + 1); d = __ldg(p + 2);
            }
            float s2 = __fadd_rn(__fadd_rn(__fmul_rn(a, a), __fmul_rn(b, b)), __fmul_rn(d, d));
            float m = sgp(__fadd_rn(sqrtf(s2), __ldg(b1 + 32 + u)));
            hv0[(u * 3 + 0) * RPC + r] = __fmul_rn(a, m);
            hv0[(u * 3 + 1) * RPC + r] = __fmul_rn(b, m);
            hv0[(u * 3 + 2) * RPC + r] = __fmul_rn(d, m);
        }
    }
    __syncthreads();

    // L1 scalar EXACT path: single pass, 4 outputs, raw direct weights
    {
        const int rg = tid & 15, og = tid >> 4, rb = rg * 4, wb = og * 4;
        u64 aA[2][2][4] = {}, aB[2][2][4] = {};
        for (int u = 0; u < S_IN; ++u) {
            ulonglong2 hu = *(const ulonglong2*)(hs0 + u * RPC + rb);
            {
                float4 w = __ldg((const float4*)(Wsss1 + (u * S_IN + u) * S_H + wb));
                DUP4(d, w);
                u64 p0 = f2mul(hu.x, hu.x), p1 = f2mul(hu.y, hu.y);
                int sp = u & 1;
                #pragma unroll
                for (int o = 0; o < 4; ++o) {
                    aA[sp][0][o] = f2fma(p0, d[o], aA[sp][0][o]);
                    aA[sp][1][o] = f2fma(p1, d[o], aA[sp][1][o]);
                }
            }
            #pragma unroll 2
            for (int v = u + 1; v < S_IN; ++v) {
                ulonglong2 hv = *(const ulonglong2*)(hs0 + v * RPC + rb);
                u64 p0 = f2mul(hu.x, hv.x), p1 = f2mul(hu.y, hv.y);
                float4 w1 = __ldg((const float4*)(Wsss1 + (u * S_IN + v) * S_H + wb));
                float4 w2 = __ldg((const float4*)(Wsss1 + (v * S_IN + u) * S_H + wb));
                DUP4(d1, w1); DUP4(d2, w2);
                int sp = v & 1;
                #pragma unroll
                for (int o = 0; o < 4; ++o) {
                    aA[sp][0][o] = f2fma(p0, d1[o], aA[sp][0][o]);
                    aA[sp][1][o] = f2fma(p1, d1[o], aA[sp][1][o]);
                }
                sp ^= 1;
                #pragma unroll
                for (int o = 0; o < 4; ++o) {
                    aA[sp][0][o] = f2fma(p0, d2[o], aA[sp][0][o]);
                    aA[sp][1][o] = f2fma(p1, d2[o], aA[sp][1][o]);
                }
            }
        }
        for (int u = 0; u < V_IN; ++u) {
            ulonglong2 h0 = *(const ulonglong2*)(hv0 + (u * 3 + 0) * RPC + rb);
            ulonglong2 h1 = *(const ulonglong2*)(hv0 + (u * 3 + 1) * RPC + rb);
            ulonglong2 h2 = *(const ulonglong2*)(hv0 + (u * 3 + 2) * RPC + rb);
            {
                float4 w = __ldg((const float4*)(Wvvs1 + (u * V_IN + u) * S_H + wb));
                DUP4(d, w);
                u64 q0 = f2fma(h2.x, h2.x, f2fma(h1.x, h1.x, f2mul(h0.x, h0.x)));
                u64 q1 = f2fma(h2.y, h2.y, f2fma(h1.y, h1.y, f2mul(h0.y, h0.y)));
                int sp = u & 1;
                #pragma unroll
                for (int o = 0; o < 4; ++o) {
                    aB[sp][0][o] = f2fma(q0, d[o], aB[sp][0][o]);
                    aB[sp][1][o] = f2fma(q1, d[o], aB[sp][1][o]);
                }
            }
            #pragma unroll 2
            for (int v = u + 1; v < V_IN; ++v) {
                ulonglong2 g0 = *(const ulonglong2*)(hv0 + (v * 3 + 0) * RPC + rb);
                ulonglong2 g1 = *(const ulonglong2*)(hv0 + (v * 3 + 1) * RPC + rb);
                ulonglong2 g2 = *(const ulonglong2*)(hv0 + (v * 3 + 2) * RPC + rb);
                u64 q0 = f2fma(h2.x, g2.x, f2fma(h1.x, g1.x, f2mul(h0.x, g0.x)));
                u64 q1 = f2fma(h2.y, g2.y, f2fma(h1.y, g1.y, f2mul(h0.y, g0.y)));
                float4 w1 = __ldg((const float4*)(Wvvs1 + (u * V_IN + v) * S_H + wb));
                float4 w2 = __ldg((const float4*)(Wvvs1 + (v * V_IN + u) * S_H + wb));
                DUP4(d1, w1); DUP4(d2, w2);
                int sp = v & 1;
                #pragma unroll
                for (int o = 0; o < 4; ++o) {
                    aB[sp][0][o] = f2fma(q0, d1[o], aB[sp][0][o]);
                    aB[sp][1][o] = f2fma(q1, d1[o], aB[sp][1][o]);
                }
                sp ^= 1;
                #pragma unroll
                for (int o = 0; o < 4; ++o) {
                    aB[sp][0][o] = f2fma(q0, d2[o], aB[sp][0][o]);
                    aB[sp][1][o] = f2fma(q1, d2[o], aB[sp][1][o]);
                }
            }
        }
        #pragma unroll
        for (int rp = 0; rp < 2; ++rp)
            #pragma unroll
            for (int o = 0; o < 4; ++o) {
                float2 A = unp(f2add(aA[0][rp][o], aA[1][rp][o]));
                float2 B = unp(f2add(aB[0][rp][o], aB[1][rp][o]));
                float zx = __fmul_rn(PW1S_C, __fadd_rn(A.x, __fmul_rn(INV3_C, B.x)));
                float zy = __fmul_rn(PW1S_C, __fadd_rn(A.y, __fmul_rn(INV3_C, B.y)));
                float hx = copysignf(sgp(fabsf(zx)), zx);
                float hy = copysignf(sgp(fabsf(zy)), zy);
                *(u64*)(hs1 + (wb + o) * RPC + rb + 2 * rp) = pk(hx, hy);
            }
    }

    // L1 vector (raw weights)
    {
        const int rg = tid & 31, og = tid >> 5, rb = rg * 2;
        const float* Wb = g_W1v + og * 4;
        u64 acc[3][4] = {};
        for (int v = 0; v < V_IN; ++v) {
            u64 hv[3];
            #pragma unroll
            for (int k = 0; k < 3; ++k) hv[k] = *(const u64*)(hv0 + (v * 3 + k) * RPC + rb);
            #pragma unroll 4
            for (int u = 0; u < S_IN; ++u) {
                float4 w = __ldg((const float4*)(Wb + (u * V_IN + v) * V_H));
                DUP4(d, w);
                u64 hu = *(const u64*)(hs0 + u * RPC + rb);
                #pragma unroll
                for (int k = 0; k < 3; ++k) {
                    u64 p = f2mul(hu, hv[k]);
                    #pragma unroll
                    for (int o = 0; o < 4; ++o) acc[k][o] = f2fma(p, d[o], acc[k][o]);
                }
            }
        }
        #pragma unroll
        for (int wi = 0; wi < 4; ++wi) {
            int w = og * 4 + wi;
            float2 a0 = unp(acc[0][wi]), a1 = unp(acc[1][wi]), a2 = unp(acc[2][wi]);
            float nx = sqrtf(a0.x * a0.x + a1.x * a1.x + a2.x * a2.x);
            float ny = sqrtf(a0.y * a0.y + a1.y * a1.y + a2.y * a2.y);
            float mx = sgp(nx) / nx, my = sgp(ny) / ny;
            *(u64*)(hv1 + (w * 3 + 0) * RPC + rb) = pk(a0.x * mx, a0.y * my);
            *(u64*)(hv1 + (w * 3 + 1) * RPC + rb) = pk(a1.x * mx, a1.y * my);
            *(u64*)(hv1 + (w * 3 + 2) * RPC + rb) = pk(a2.x * mx, a2.y * my);
        }
    }
    __syncthreads();

    // L2 scalar (raw weights)
    {
        const int rg = tid & 31, og = tid >> 5, rb = rg * 2;
        const float* Wb = g_W2s + og * 4;
        u64 acc[4] = {};
        int f = 0;
        for (int u = 0; u < S_H; ++u) {
            u64 hu = *(const u64*)(hs1 + u * RPC + rb);
            #pragma unroll 4
            for (int v = u; v < S_H; ++v, ++f) {
                float4 w = __ldg((const float4*)(Wb + f * S_OUT));
                DUP4(d, w);
                u64 hv = *(const u64*)(hs1 + v * RPC + rb);
                u64 p = f2mul(hu, hv);
                #pragma unroll
                for (int o = 0; o < 4; ++o) acc[o] = f2fma(p, d[o], acc[o]);
            }
        }
        for (int u = 0; u < V_H; ++u) {
            u64 h0 = *(const u64*)(hv1 + (u * 3 + 0) * RPC + rb);
            u64 h1 = *(const u64*)(hv1 + (u * 3 + 1) * RPC + rb);
            u64 h2 = *(const u64*)(hv1 + (u * 3 + 2) * RPC + rb);
            #pragma unroll 4
            for (int v = u; v < V_H; ++v, ++f) {
                float4 w = __ldg((const float4*)(Wb + f * S_OUT));
                DUP4(d, w);
                u64 g0 = *(const u64*)(hv1 + (v * 3 + 0) * RPC + rb);
                u64 g1 = *(const u64*)(hv1 + (v * 3 + 1) * RPC + rb);
                u64 g2 = *(const u64*)(hv1 + (v * 3 + 2) * RPC + rb);
                u64 p = f2mul(h0, g0); p = f2fma(h1, g1, p); p = f2fma(h2, g2, p);
                #pragma unroll
                for (int o = 0; o < 4; ++o) acc[o] = f2fma(p, d[o], acc[o]);
            }
        }
        int n0 = row0 + rb, n1 = n0 + 1;
        #pragma unroll
        for (int wi = 0; wi < 4; ++wi) {
            int w = og * 4 + wi;
            float bw = __ldg(b3 + w);
            float2 z = unp(acc[wi]);
            if (n0 < N) out[(size_t)n0 * 80 + w] = z.x * sgp(fabsf(z.x) + bw);
            if (n1 < N) out[(size_t)n1 * 80 + w] = z.y * sgp(fabsf(z.y) + bw);
        }
    }

    // L2 vector (dup weights, unchanged)
    {
        const int rg = tid & 31, og = tid >> 5, rb = rg * 2;
        const float2* Wb = g_W2v + og * 2;
        u64 acc[3][2] = {};
        for (int v = 0; v < V_H; ++v) {
            u64 hv[3];
            #pragma unroll
            for (int k = 0; k < 3; ++k) hv[k] = *(const u64*)(hv1 + (v * 3 + k) * RPC + rb);
            #pragma unroll 4
            for (int u = 0; u < S_H; ++u) {
                ulonglong2 wv = __ldg((const ulonglong2*)(Wb + (u * V_H + v) * V_OUT));
                u64 hu = *(const u64*)(hs1 + u * RPC + rb);
                #pragma unroll
                for (int k = 0; k < 3; ++k) {
                    u64 p = f2mul(hu, hv[k]);
                    acc[k][0] = f2fma(p, wv.x, acc[k][0]);
                    acc[k][1] = f2fma(p, wv.y, acc[k][1]);
                }
            }
        }
        int n0 = row0 + rb, n1 = n0 + 1;
        #pragma unroll
        for (int wi = 0; wi < 2; ++wi) {
            int w = og * 2 + wi;
            float bw = __ldg(b3 + 32 + w);
            float2 a0 = unp(acc[0][wi]), a1 = unp(acc[1][wi]), a2 = unp(acc[2][wi]);
            float mx = sgp(sqrtf(a0.x * a0.x + a1.x * a1.x + a2.x * a2.x) + bw);
            float my = sgp(sqrtf(a0.y * a0.y + a1.y * a1.y + a2.y * a2.y) + bw);
            if (n0 < N) {
                float* o = out + (size_t)n0 * 80 + 32 + 3 * w;
                o[0] = a0.x * mx; o[1] = a1.x * mx; o[2] = a2.x * mx;
            }
            if (n1 < N) {
                float* o = out + (size_t)n1 * 80 + 32 + 3 * w;
                o[0] = a0.y * my; o[1] = a1.y * my; o[2] = a2.y * my;
            }
        }
    }
}

extern "C" void kernel_launch(void* const* d_in, const int* in_sizes, int n_in,
                              void* d_out, int out_size) {
    const float* x     = (const float*)d_in[0];
    const float* Wsss1 = (const float*)d_in[1];
    const float* Wvvs1 = (const float*)d_in[2];
    const float* Wsvv1 = (const float*)d_in[3];
    const float* Wvsv1 = (const float*)d_in[4];
    const float* Wsss2 = (const float*)d_in[5];
    const float* Wvvs2 = (const float*)d_in[6];
    const float* Wsvv2 = (const float*)d_in[7];
    const float* Wvsv2 = (const float*)d_in[8];
    const float* b1    = (const float*)d_in[9];
    const float* b3    = (const float*)d_in[10];
    float* out = (float*)d_out;
    int N = in_sizes[0] / 80;

    prep_all<<<832, 256>>>(Wsvv1, Wvsv1, Wsss2, Wvvs2, Wsvv2, Wvsv2);

    const int smem = 240 * RPC * sizeof(float);  // 61440 B
    cudaFuncSetAttribute(dl_main, cudaFuncAttributeMaxDynamicSharedMemorySize, smem);
    int blocks = (N + RPC - 1) / RPC;
    dl_main<<<blocks, TPB, smem>>>(x, Wsss1, Wvvs1, b1, b3, out, N);
}

// round 14
// speedup vs baseline: 1.4178x; 1.1122x over previous
#include <cuda_runtime.h>
#include <math.h>

#define S_IN 32
#define V_IN 16
#define S_H  64
#define V_H  32
#define S_OUT 32
#define V_OUT 16
#define NF2_SS 2080
#define NF2    2608
#define RPC 64
#define TPB 256
#define PW1S_C  0.02795084971874737f
#define INV3_C  0.5773502691896258f
#define PW2S  0.0139754248593737f
#define PW2S3 0.0080687153045988f
#define CW1V  0.03125f
#define CW2V  0.015625f

typedef unsigned long long u64;

__device__ __align__(16) float  g_W1v[S_IN * V_IN * V_H];   // raw, scaled
__device__ __align__(16) float  g_W2s[NF2 * S_OUT];         // raw, folded+scaled
__device__ __align__(16) float2 g_W2v[S_H * V_H * V_OUT];   // dup, fused+scaled

__device__ __forceinline__ u64 f2mul(u64 a, u64 b) {
    u64 r; asm("mul.rn.f32x2 %0,%1,%2;" : "=l"(r) : "l"(a), "l"(b)); return r;
}
__device__ __forceinline__ u64 f2add(u64 a, u64 b) {
    u64 r; asm("add.rn.f32x2 %0,%1,%2;" : "=l"(r) : "l"(a), "l"(b)); return r;
}
__device__ __forceinline__ u64 f2fma(u64 a, u64 b, u64 c) {
    u64 r; asm("fma.rn.f32x2 %0,%1,%2,%3;" : "=l"(r) : "l"(a), "l"(b), "l"(c)); return r;
}
__device__ __forceinline__ float2 unp(u64 v) {
    return make_float2(__uint_as_float((unsigned)v), __uint_as_float((unsigned)(v >> 32)));
}
__device__ __forceinline__ u64 pk(float x, float y) {
    return (u64)__float_as_uint(x) | ((u64)__float_as_uint(y) << 32);
}
__device__ __forceinline__ u64 dupf(float w) {
    u64 b = (u64)__float_as_uint(w); return b | (b << 32);
}
// XLA logistic: 0.5 + 0.5*tanh(0.5*x)
__device__ __forceinline__ float sgp(float a) {
    float t = tanhf(__fmul_rn(a, 0.5f));
    return __fadd_rn(0.5f, __fmul_rn(0.5f, t));
}

#define DUP4(d, W_) u64 d[4] = {dupf((W_).x), dupf((W_).y), dupf((W_).z), dupf((W_).w)}

// ---- fused prep: 212992 items = 832 x 256 ----
__global__ void prep_all(const float* __restrict__ Wsvv1, const float* __restrict__ Wvsv1,
                         const float* __restrict__ Wsss2, const float* __restrict__ Wvvs2,
                         const float* __restrict__ Wsvv2, const float* __restrict__ Wvsv2)
{
    int i = blockIdx.x * blockDim.x + threadIdx.x;
    if (i < 16384) {                                  // w1v raw fused
        int w = i & 31, uv = i >> 5, u = uv >> 4, v = uv & 15;
        g_W1v[i] = CW1V * (Wsvv1[(u * V_IN + v) * V_H + w] + Wvsv1[(v * S_IN + u) * V_H + w]);
        return;
    }
    i -= 16384;
    if (i < 131072) {                                 // w2s ss folded raw
        int w = i & 31, uv = i >> 5, u = uv >> 6, v = uv & 63;
        if (v >= u) {
            int f = u * S_H - (u * (u - 1)) / 2 + (v - u);
            float val = Wsss2[(u * S_H + v) * S_OUT + w];
            if (v > u) val += Wsss2[(v * S_H + u) * S_OUT + w];
            g_W2s[f * S_OUT + w] = val * PW2S;
        }
        return;
    }
    i -= 131072;
    if (i < 32768) {                                  // w2s vv folded raw
        int w = i & 31, uv = i >> 5, u = uv >> 5, v = uv & 31;
        if (v >= u) {
            int f = NF2_SS + u * V_H - (u * (u - 1)) / 2 + (v - u);
            float val = Wvvs2[(u * V_H + v) * S_OUT + w];
            if (v > u) val += Wvvs2[(v * V_H + u) * S_OUT + w];
            g_W2s[f * S_OUT + w] = val * PW2S3;
        }
        return;
    }
    i -= 32768;
    if (i < 32768) {                                  // w2v dup fused
        int w = i & 15, uv = i >> 4, u = uv >> 5, v = uv & 31;
        float val = CW2V * (Wsvv2[(u * V_H + v) * V_OUT + w] + Wvsv2[(v * S_H + u) * V_OUT + w]);
        g_W2v[i] = make_float2(val, val);
    }
}

// ---- main fused kernel ----
__global__ void __launch_bounds__(TPB, 2)
dl_main(const float* __restrict__ x,
        const float* __restrict__ Wsss1, const float* __restrict__ Wvvs1,
        const float* __restrict__ b1, const float* __restrict__ b3,
        float* __restrict__ out, int N)
{
    extern __shared__ float sm[];
    float* hs0 = sm;                     // [32][RPC]
    float* hv0 = hs0 + S_IN * RPC;       // [48][RPC]
    float* hs1 = hv0 + 3 * V_IN * RPC;   // [64][RPC]
    float* hv1 = hs1 + S_H * RPC;        // [96][RPC]
    const int tid = threadIdx.x;
    const int row0 = blockIdx.x * RPC;

    // stage 0 (UNCHANGED — bit-exact)
    for (int idx = tid; idx < RPC * 48; idx += TPB) {
        int r = idx / 48, c = idx - r * 48, n = row0 + r;
        if (c < S_IN) {
            float v = (n < N) ? __ldg(x + (size_t)n * 80 + c) : 0.f;
            float m = sgp(__fadd_rn(fabsf(v), __ldg(b1 + c)));
            hs0[c * RPC + r] = __fmul_rn(v, m);
        } else {
            int u = c - S_IN;
            float a = 0.f, b = 0.f, d = 0.f;
            if (n < N) {
                const float* p = x + (size_t)n * 80 + 32 + 3 * u;
                a = __ldg(p); b = __ldg(p + 1); d = __ldg(p + 2);
            }
            float s2 = __fadd_rn(__fadd_rn(__fmul_rn(a, a), __fmul_rn(b, b)), __fmul_rn(d, d));
            float m = sgp(__fadd_rn(sqrtf(s2), __ldg(b1 + 32 + u)));
            hv0[(u * 3 + 0) * RPC + r] = __fmul_rn(a, m);
            hv0[(u * 3 + 1) * RPC + r] = __fmul_rn(b, m);
            hv0[(u * 3 + 2) * RPC + r] = __fmul_rn(d, m);
        }
    }
    __syncthreads();

    // L1 scalar EXACT path (UNCHANGED — flip-sensitive, do not reorder)
    {
        const int rg = tid & 15, og = tid >> 4, rb = rg * 4, wb = og * 4;
        u64 aA[2][2][4] = {}, aB[2][2][4] = {};
        for (int u = 0; u < S_IN; ++u) {
            ulonglong2 hu = *(const ulonglong2*)(hs0 + u * RPC + rb);
            {
                float4 w = __ldg((const float4*)(Wsss1 + (u * S_IN + u) * S_H + wb));
                DUP4(d, w);
                u64 p0 = f2mul(hu.x, hu.x), p1 = f2mul(hu.y, hu.y);
                int sp = u & 1;
                #pragma unroll
                for (int o = 0; o < 4; ++o) {
                    aA[sp][0][o] = f2fma(p0, d[o], aA[sp][0][o]);
                    aA[sp][1][o] = f2fma(p1, d[o], aA[sp][1][o]);
                }
            }
            #pragma unroll 2
            for (int v = u + 1; v < S_IN; ++v) {
                ulonglong2 hv = *(const ulonglong2*)(hs0 + v * RPC + rb);
                u64 p0 = f2mul(hu.x, hv.x), p1 = f2mul(hu.y, hv.y);
                float4 w1 = __ldg((const float4*)(Wsss1 + (u * S_IN + v) * S_H + wb));
                float4 w2 = __ldg((const float4*)(Wsss1 + (v * S_IN + u) * S_H + wb));
                DUP4(d1, w1); DUP4(d2, w2);
                int sp = v & 1;
                #pragma unroll
                for (int o = 0; o < 4; ++o) {
                    aA[sp][0][o] = f2fma(p0, d1[o], aA[sp][0][o]);
                    aA[sp][1][o] = f2fma(p1, d1[o], aA[sp][1][o]);
                }
                sp ^= 1;
                #pragma unroll
                for (int o = 0; o < 4; ++o) {
                    aA[sp][0][o] = f2fma(p0, d2[o], aA[sp][0][o]);
                    aA[sp][1][o] = f2fma(p1, d2[o], aA[sp][1][o]);
                }
            }
        }
        for (int u = 0; u < V_IN; ++u) {
            ulonglong2 h0 = *(const ulonglong2*)(hv0 + (u * 3 + 0) * RPC + rb);
            ulonglong2 h1 = *(const ulonglong2*)(hv0 + (u * 3 + 1) * RPC + rb);
            ulonglong2 h2 = *(const ulonglong2*)(hv0 + (u * 3 + 2) * RPC + rb);
            {
                float4 w = __ldg((const float4*)(Wvvs1 + (u * V_IN + u) * S_H + wb));
                DUP4(d, w);
                u64 q0 = f2fma(h2.x, h2.x, f2fma(h1.x, h1.x, f2mul(h0.x, h0.x)));
                u64 q1 = f2fma(h2.y, h2.y, f2fma(h1.y, h1.y, f2mul(h0.y, h0.y)));
                int sp = u & 1;
                #pragma unroll
                for (int o = 0; o < 4; ++o) {
                    aB[sp][0][o] = f2fma(q0, d[o], aB[sp][0][o]);
                    aB[sp][1][o] = f2fma(q1, d[o], aB[sp][1][o]);
                }
            }
            #pragma unroll 2
            for (int v = u + 1; v < V_IN; ++v) {
                ulonglong2 g0 = *(const ulonglong2*)(hv0 + (v * 3 + 0) * RPC + rb);
                ulonglong2 g1 = *(const ulonglong2*)(hv0 + (v * 3 + 1) * RPC + rb);
                ulonglong2 g2 = *(const ulonglong2*)(hv0 + (v * 3 + 2) * RPC + rb);
                u64 q0 = f2fma(h2.x, g2.x, f2fma(h1.x, g1.x, f2mul(h0.x, g0.x)));
                u64 q1 = f2fma(h2.y, g2.y, f2fma(h1.y, g1.y, f2mul(h0.y, g0.y)));
                float4 w1 = __ldg((const float4*)(Wvvs1 + (u * V_IN + v) * S_H + wb));
                float4 w2 = __ldg((const float4*)(Wvvs1 + (v * V_IN + u) * S_H + wb));
                DUP4(d1, w1); DUP4(d2, w2);
                int sp = v & 1;
                #pragma unroll
                for (int o = 0; o < 4; ++o) {
                    aB[sp][0][o] = f2fma(q0, d1[o], aB[sp][0][o]);
                    aB[sp][1][o] = f2fma(q1, d1[o], aB[sp][1][o]);
                }
                sp ^= 1;
                #pragma unroll
                for (int o = 0; o < 4; ++o) {
                    aB[sp][0][o] = f2fma(q0, d2[o], aB[sp][0][o]);
                    aB[sp][1][o] = f2fma(q1, d2[o], aB[sp][1][o]);
                }
            }
        }
        #pragma unroll
        for (int rp = 0; rp < 2; ++rp)
            #pragma unroll
            for (int o = 0; o < 4; ++o) {
                float2 A = unp(f2add(aA[0][rp][o], aA[1][rp][o]));
                float2 B = unp(f2add(aB[0][rp][o], aB[1][rp][o]));
                float zx = __fmul_rn(PW1S_C, __fadd_rn(A.x, __fmul_rn(INV3_C, B.x)));
                float zy = __fmul_rn(PW1S_C, __fadd_rn(A.y, __fmul_rn(INV3_C, B.y)));
                float hx = copysignf(sgp(fabsf(zx)), zx);
                float hy = copysignf(sgp(fabsf(zy)), zy);
                *(u64*)(hs1 + (wb + o) * RPC + rb + 2 * rp) = pk(hx, hy);
            }
    }

    // L1 vector (UNCHANGED)
    {
        const int rg = tid & 31, og = tid >> 5, rb = rg * 2;
        const float* Wb = g_W1v + og * 4;
        u64 acc[3][4] = {};
        for (int v = 0; v < V_IN; ++v) {
            u64 hv[3];
            #pragma unroll
            for (int k = 0; k < 3; ++k) hv[k] = *(const u64*)(hv0 + (v * 3 + k) * RPC + rb);
            #pragma unroll 4
            for (int u = 0; u < S_IN; ++u) {
                float4 w = __ldg((const float4*)(Wb + (u * V_IN + v) * V_H));
                DUP4(d, w);
                u64 hu = *(const u64*)(hs0 + u * RPC + rb);
                #pragma unroll
                for (int k = 0; k < 3; ++k) {
                    u64 p = f2mul(hu, hv[k]);
                    #pragma unroll
                    for (int o = 0; o < 4; ++o) acc[k][o] = f2fma(p, d[o], acc[k][o]);
                }
            }
        }
        #pragma unroll
        for (int wi = 0; wi < 4; ++wi) {
            int w = og * 4 + wi;
            float2 a0 = unp(acc[0][wi]), a1 = unp(acc[1][wi]), a2 = unp(acc[2][wi]);
            float nx = sqrtf(a0.x * a0.x + a1.x * a1.x + a2.x * a2.x);
            float ny = sqrtf(a0.y * a0.y + a1.y * a1.y + a2.y * a2.y);
            float mx = sgp(nx) / nx, my = sgp(ny) / ny;
            *(u64*)(hv1 + (w * 3 + 0) * RPC + rb) = pk(a0.x * mx, a0.y * my);
            *(u64*)(hv1 + (w * 3 + 1) * RPC + rb) = pk(a1.x * mx, a1.y * my);
            *(u64*)(hv1 + (w * 3 + 2) * RPC + rb) = pk(a2.x * mx, a2.y * my);
        }
    }
    __syncthreads();

    // L2 scalar — RESTRUCTURED: u-tiled by 4 (continuous gate, order-free)
    {
        const int rg = tid & 31, og = tid >> 5, rb = rg * 2;
        const float* Wb = g_W2s + og * 4;
        u64 acc[4] = {};
        // ss part: pairs u<=v, f(u,v) = fb(u) + v, fb(u) = u*S_H - u(u-1)/2 - u
        for (int u0 = 0; u0 < S_H; u0 += 4) {
            u64 hu[4]; int fb[4];
            #pragma unroll
            for (int i = 0; i < 4; ++i) {
                int u = u0 + i;
                hu[i] = *(const u64*)(hs1 + u * RPC + rb);
                fb[i] = u * S_H - (u * (u - 1)) / 2 - u;
            }
            // corner pairs inside tile
            #pragma unroll
            for (int i = 0; i < 4; ++i)
                #pragma unroll
                for (int j = i; j < 4; ++j) {
                    float4 w = __ldg((const float4*)(Wb + (fb[i] + u0 + j) * S_OUT));
                    DUP4(d, w);
                    u64 p = f2mul(hu[i], hu[j]);
                    #pragma unroll
                    for (int o = 0; o < 4; ++o) acc[o] = f2fma(p, d[o], acc[o]);
                }
            #pragma unroll 2
            for (int v = u0 + 4; v < S_H; ++v) {
                u64 hv = *(const u64*)(hs1 + v * RPC + rb);
                #pragma unroll
                for (int i = 0; i < 4; ++i) {
                    float4 w = __ldg((const float4*)(Wb + (fb[i] + v) * S_OUT));
                    DUP4(d, w);
                    u64 p = f2mul(hu[i], hv);
                    #pragma unroll
                    for (int o = 0; o < 4; ++o) acc[o] = f2fma(p, d[o], acc[o]);
                }
            }
        }
        // vv part: fvv(u,v) = fbv(u) + v, fbv(u) = NF2_SS + u*V_H - u(u-1)/2 - u
        for (int u0 = 0; u0 < V_H; u0 += 4) {
            u64 h[4][3]; int fb[4];
            #pragma unroll
            for (int i = 0; i < 4; ++i) {
                int u = u0 + i;
                #pragma unroll
                for (int k = 0; k < 3; ++k)
                    h[i][k] = *(const u64*)(hv1 + (u * 3 + k) * RPC + rb);
                fb[i] = NF2_SS + u * V_H - (u * (u - 1)) / 2 - u;
            }
            #pragma unroll
            for (int i = 0; i < 4; ++i)
                #pragma unroll
                for (int j = i; j < 4; ++j) {
                    float4 w = __ldg((const float4*)(Wb + (fb[i] + u0 + j) * S_OUT));
                    DUP4(d, w);
                    u64 q = f2fma(h[i][2], h[j][2], f2fma(h[i][1], h[j][1], f2mul(h[i][0], h[j][0])));
                    #pragma unroll
                    for (int o = 0; o < 4; ++o) acc[o] = f2fma(q, d[o], acc[o]);
                }
            #pragma unroll 2
            for (int v = u0 + 4; v < V_H; ++v) {
                u64 g0 = *(const u64*)(hv1 + (v * 3 + 0) * RPC + rb);
                u64 g1 = *(const u64*)(hv1 + (v * 3 + 1) * RPC + rb);
                u64 g2 = *(const u64*)(hv1 + (v * 3 + 2) * RPC + rb);
                #pragma unroll
                for (int i = 0; i < 4; ++i) {
                    float4 w = __ldg((const float4*)(Wb + (fb[i] + v) * S_OUT));
                    DUP4(d, w);
                    u64 q = f2fma(h[i][2], g2, f2fma(h[i][1], g1, f2mul(h[i][0], g0)));
                    #pragma unroll
                    for (int o = 0; o < 4; ++o) acc[o] = f2fma(q, d[o], acc[o]);
                }
            }
        }
        int n0 = row0 + rb, n1 = n0 + 1;
        #pragma unroll
        for (int wi = 0; wi < 4; ++wi) {
            int w = og * 4 + wi;
            float bw = __ldg(b3 + w);
            float2 z = unp(acc[wi]);
            if (n0 < N) out[(size_t)n0 * 80 + w] = z.x * sgp(fabsf(z.x) + bw);
            if (n1 < N) out[(size_t)n1 * 80 + w] = z.y * sgp(fabsf(z.y) + bw);
        }
    }

    // L2 vector — RESTRUCTURED: v-tiled by 4 (continuous, order-free)
    {
        const int rg = tid & 31, og = tid >> 5, rb = rg * 2;
        const float2* Wb = g_W2v + og * 2;
        u64 acc[3][2] = {};
        for (int v0 = 0; v0 < V_H; v0 += 4) {
            u64 hv[4][3];
            #pragma unroll
            for (int j = 0; j < 4; ++j)
                #pragma unroll
                for (int k = 0; k < 3; ++k)
                    hv[j][k] = *(const u64*)(hv1 + ((v0 + j) * 3 + k) * RPC + rb);
            #pragma unroll 2
            for (int u = 0; u < S_H; ++u) {
                u64 hu = *(const u64*)(hs1 + u * RPC + rb);
                #pragma unroll
                for (int j = 0; j < 4; ++j) {
                    ulonglong2 wv = __ldg((const ulonglong2*)(Wb + (u * V_H + v0 + j) * V_OUT));
                    #pragma unroll
                    for (int k = 0; k < 3; ++k) {
                        u64 p = f2mul(hu, hv[j][k]);
                        acc[k][0] = f2fma(p, wv.x, acc[k][0]);
                        acc[k][1] = f2fma(p, wv.y, acc[k][1]);
                    }
                }
            }
        }
        int n0 = row0 + rb, n1 = n0 + 1;
        #pragma unroll
        for (int wi = 0; wi < 2; ++wi) {
            int w = og * 2 + wi;
            float bw = __ldg(b3 + 32 + w);
            float2 a0 = unp(acc[0][wi]), a1 = unp(acc[1][wi]), a2 = unp(acc[2][wi]);
            float mx = sgp(sqrtf(a0.x * a0.x + a1.x * a1.x + a2.x * a2.x) + bw);
            float my = sgp(sqrtf(a0.y * a0.y + a1.y * a1.y + a2.y * a2.y) + bw);
            if (n0 < N) {
                float* o = out + (size_t)n0 * 80 + 32 + 3 * w;
                o[0] = a0.x * mx; o[1] = a1.x * mx; o[2] = a2.x * mx;
            }
            if (n1 < N) {
                float* o = out + (size_t)n1 * 80 + 32 + 3 * w;
                o[0] = a0.y * my; o[1] = a1.y * my; o[2] = a2.y * my;
            }
        }
    }
}

extern "C" void kernel_launch(void* const* d_in, const int* in_sizes, int n_in,
                              void* d_out, int out_size) {
    const float* x     = (const float*)d_in[0];
    const float* Wsss1 = (const float*)d_in[1];
    const float* Wvvs1 = (const float*)d_in[2];
    const float* Wsvv1 = (const float*)d_in[3];
    const float* Wvsv1 = (const float*)d_in[4];
    const float* Wsss2 = (const float*)d_in[5];
    const float* Wvvs2 = (const float*)d_in[6];
    const float* Wsvv2 = (const float*)d_in[7];
    const float* Wvsv2 = (const float*)d_in[8];
    const float* b1    = (const float*)d_in[9];
    const float* b3    = (const float*)d_in[10];
    float* out = (float*)d_out;
    int N = in_sizes[0] / 80;

    prep_all<<<832, 256>>>(Wsvv1, Wvsv1, Wsss2, Wvvs2, Wsvv2, Wvsv2);

    const int smem = 240 * RPC * sizeof(float);  // 61440 B
    cudaFuncSetAttribute(dl_main, cudaFuncAttributeMaxDynamicSharedMemorySize, smem);
    int blocks = (N + RPC - 1) / RPC;
    dl_main<<<blocks, TPB, smem>>>(x, Wsss1, Wvvs1, b1, b3, out, N);
}

// round 16
// speedup vs baseline: 1.4670x; 1.0347x over previous
#include <cuda_runtime.h>
#include <math.h>

#define S_IN 32
#define V_IN 16
#define S_H  64
#define V_H  32
#define S_OUT 32
#define V_OUT 16
#define NF2_SS 2080
#define NF2    2608
#define RPC 64
#define TPB 256
#define PW1S_C  0.02795084971874737f
#define INV3_C  0.5773502691896258f
#define PW2S  0.0139754248593737f
#define PW2S3 0.0080687153045988f
#define CW1V  0.03125f
#define CW2V  0.015625f

typedef unsigned long long u64;

__device__ __align__(16) float  g_W1v[S_IN * V_IN * V_H];   // raw, scaled
__device__ __align__(16) float  g_W2s[NF2 * S_OUT];         // raw, folded+scaled
__device__ __align__(16) float2 g_W2v[S_H * V_H * V_OUT];   // dup, fused+scaled

__device__ __forceinline__ u64 f2mul(u64 a, u64 b) {
    u64 r; asm("mul.rn.f32x2 %0,%1,%2;" : "=l"(r) : "l"(a), "l"(b)); return r;
}
__device__ __forceinline__ u64 f2add(u64 a, u64 b) {
    u64 r; asm("add.rn.f32x2 %0,%1,%2;" : "=l"(r) : "l"(a), "l"(b)); return r;
}
__device__ __forceinline__ u64 f2fma(u64 a, u64 b, u64 c) {
    u64 r; asm("fma.rn.f32x2 %0,%1,%2,%3;" : "=l"(r) : "l"(a), "l"(b), "l"(c)); return r;
}
__device__ __forceinline__ float2 unp(u64 v) {
    return make_float2(__uint_as_float((unsigned)v), __uint_as_float((unsigned)(v >> 32)));
}
__device__ __forceinline__ u64 pk(float x, float y) {
    return (u64)__float_as_uint(x) | ((u64)__float_as_uint(y) << 32);
}
__device__ __forceinline__ u64 dupf(float w) {
    u64 b = (u64)__float_as_uint(w); return b | (b << 32);
}
// XLA logistic: 0.5 + 0.5*tanh(0.5*x)
__device__ __forceinline__ float sgp(float a) {
    float t = tanhf(__fmul_rn(a, 0.5f));
    return __fadd_rn(0.5f, __fmul_rn(0.5f, t));
}

#define DUP4(d, W_) u64 d[4] = {dupf((W_).x), dupf((W_).y), dupf((W_).z), dupf((W_).w)}

// ---- fused prep: 212992 items = 832 x 256 ----
__global__ void prep_all(const float* __restrict__ Wsvv1, const float* __restrict__ Wvsv1,
                         const float* __restrict__ Wsss2, const float* __restrict__ Wvvs2,
                         const float* __restrict__ Wsvv2, const float* __restrict__ Wvsv2)
{
    int i = blockIdx.x * blockDim.x + threadIdx.x;
    if (i < 16384) {                                  // w1v raw fused
        int w = i & 31, uv = i >> 5, u = uv >> 4, v = uv & 15;
        g_W1v[i] = CW1V * (Wsvv1[(u * V_IN + v) * V_H + w] + Wvsv1[(v * S_IN + u) * V_H + w]);
        return;
    }
    i -= 16384;
    if (i < 131072) {                                 // w2s ss folded raw
        int w = i & 31, uv = i >> 5, u = uv >> 6, v = uv & 63;
        if (v >= u) {
            int f = u * S_H - (u * (u - 1)) / 2 + (v - u);
            float val = Wsss2[(u * S_H + v) * S_OUT + w];
            if (v > u) val += Wsss2[(v * S_H + u) * S_OUT + w];
            g_W2s[f * S_OUT + w] = val * PW2S;
        }
        return;
    }
    i -= 131072;
    if (i < 32768) {                                  // w2s vv folded raw
        int w = i & 31, uv = i >> 5, u = uv >> 5, v = uv & 31;
        if (v >= u) {
            int f = NF2_SS + u * V_H - (u * (u - 1)) / 2 + (v - u);
            float val = Wvvs2[(u * V_H + v) * S_OUT + w];
            if (v > u) val += Wvvs2[(v * V_H + u) * S_OUT + w];
            g_W2s[f * S_OUT + w] = val * PW2S3;
        }
        return;
    }
    i -= 32768;
    if (i < 32768) {                                  // w2v dup fused
        int w = i & 15, uv = i >> 4, u = uv >> 5, v = uv & 31;
        float val = CW2V * (Wsvv2[(u * V_H + v) * V_OUT + w] + Wvsv2[(v * S_H + u) * V_OUT + w]);
        g_W2v[i] = make_float2(val, val);
    }
}

// ---- main fused kernel (numerics identical to R14-pass) ----
__global__ void __launch_bounds__(TPB, 3)
dl_main(const float* __restrict__ x,
        const float* __restrict__ Wsss1, const float* __restrict__ Wvvs1,
        const float* __restrict__ b1, const float* __restrict__ b3,
        float* __restrict__ out, int N)
{
    extern __shared__ float sm[];
    float* hs0 = sm;                     // [32][RPC]
    float* hv0 = hs0 + S_IN * RPC;       // [48][RPC]
    float* hs1 = hv0 + 3 * V_IN * RPC;   // [64][RPC]
    float* hv1 = hs1 + S_H * RPC;        // [96][RPC]
    const int tid = threadIdx.x;
    const int row0 = blockIdx.x * RPC;

    // stage 0 (bit-exact)
    for (int idx = tid; idx < RPC * 48; idx += TPB) {
        int r = idx / 48, c = idx - r * 48, n = row0 + r;
        if (c < S_IN) {
            float v = (n < N) ? __ldg(x + (size_t)n * 80 + c) : 0.f;
            float m = sgp(__fadd_rn(fabsf(v), __ldg(b1 + c)));
            hs0[c * RPC + r] = __fmul_rn(v, m);
        } else {
            int u = c - S_IN;
            float a = 0.f, b = 0.f, d = 0.f;
            if (n < N) {
                const float* p = x + (size_t)n * 80 + 32 + 3 * u;
                a = __ldg(p); b = __ldg(p + 1); d = __ldg(p + 2);
            }
            float s2 = __fadd_rn(__fadd_rn(__fmul_rn(a, a), __fmul_rn(b, b)), __fmul_rn(d, d));
            float m = sgp(__fadd_rn(sqrtf(s2), __ldg(b1 + 32 + u)));
            hv0[(u * 3 + 0) * RPC + r] = __fmul_rn(a, m);
            hv0[(u * 3 + 1) * RPC + r] = __fmul_rn(b, m);
            hv0[(u * 3 + 2) * RPC + r] = __fmul_rn(d, m);
        }
    }
    __syncthreads();

    // L1 scalar EXACT path (R14 version — flip-sensitive, 16rg x 4rows, 16og x 4outs)
    {
        const int rg = tid & 15, og = tid >> 4, rb = rg * 4, wb = og * 4;
        u64 aA[2][2][4] = {}, aB[2][2][4] = {};
        for (int u = 0; u < S_IN; ++u) {
            ulonglong2 hu = *(const ulonglong2*)(hs0 + u * RPC + rb);
            {
                float4 w = __ldg((const float4*)(Wsss1 + (u * S_IN + u) * S_H + wb));
                DUP4(d, w);
                u64 p0 = f2mul(hu.x, hu.x), p1 = f2mul(hu.y, hu.y);
                int sp = u & 1;
                #pragma unroll
                for (int o = 0; o < 4; ++o) {
                    aA[sp][0][o] = f2fma(p0, d[o], aA[sp][0][o]);
                    aA[sp][1][o] = f2fma(p1, d[o], aA[sp][1][o]);
                }
            }
            #pragma unroll 2
            for (int v = u + 1; v < S_IN; ++v) {
                ulonglong2 hv = *(const ulonglong2*)(hs0 + v * RPC + rb);
                u64 p0 = f2mul(hu.x, hv.x), p1 = f2mul(hu.y, hv.y);
                float4 w1 = __ldg((const float4*)(Wsss1 + (u * S_IN + v) * S_H + wb));
                float4 w2 = __ldg((const float4*)(Wsss1 + (v * S_IN + u) * S_H + wb));
                DUP4(d1, w1); DUP4(d2, w2);
                int sp = v & 1;
                #pragma unroll
                for (int o = 0; o < 4; ++o) {
                    aA[sp][0][o] = f2fma(p0, d1[o], aA[sp][0][o]);
                    aA[sp][1][o] = f2fma(p1, d1[o], aA[sp][1][o]);
                }
                sp ^= 1;
                #pragma unroll
                for (int o = 0; o < 4; ++o) {
                    aA[sp][0][o] = f2fma(p0, d2[o], aA[sp][0][o]);
                    aA[sp][1][o] = f2fma(p1, d2[o], aA[sp][1][o]);
                }
            }
        }
        for (int u = 0; u < V_IN; ++u) {
            ulonglong2 h0 = *(const ulonglong2*)(hv0 + (u * 3 + 0) * RPC + rb);
            ulonglong2 h1 = *(const ulonglong2*)(hv0 + (u * 3 + 1) * RPC + rb);
            ulonglong2 h2 = *(const ulonglong2*)(hv0 + (u * 3 + 2) * RPC + rb);
            {
                float4 w = __ldg((const float4*)(Wvvs1 + (u * V_IN + u) * S_H + wb));
                DUP4(d, w);
                u64 q0 = f2fma(h2.x, h2.x, f2fma(h1.x, h1.x, f2mul(h0.x, h0.x)));
                u64 q1 = f2fma(h2.y, h2.y, f2fma(h1.y, h1.y, f2mul(h0.y, h0.y)));
                int sp = u & 1;
                #pragma unroll
                for (int o = 0; o < 4; ++o) {
                    aB[sp][0][o] = f2fma(q0, d[o], aB[sp][0][o]);
                    aB[sp][1][o] = f2fma(q1, d[o], aB[sp][1][o]);
                }
            }
            #pragma unroll 2
            for (int v = u + 1; v < V_IN; ++v) {
                ulonglong2 g0 = *(const ulonglong2*)(hv0 + (v * 3 + 0) * RPC + rb);
                ulonglong2 g1 = *(const ulonglong2*)(hv0 + (v * 3 + 1) * RPC + rb);
                ulonglong2 g2 = *(const ulonglong2*)(hv0 + (v * 3 + 2) * RPC + rb);
                u64 q0 = f2fma(h2.x, g2.x, f2fma(h1.x, g1.x, f2mul(h0.x, g0.x)));
                u64 q1 = f2fma(h2.y, g2.y, f2fma(h1.y, g1.y, f2mul(h0.y, g0.y)));
                float4 w1 = __ldg((const float4*)(Wvvs1 + (u * V_IN + v) * S_H + wb));
                float4 w2 = __ldg((const float4*)(Wvvs1 + (v * V_IN + u) * S_H + wb));
                DUP4(d1, w1); DUP4(d2, w2);
                int sp = v & 1;
                #pragma unroll
                for (int o = 0; o < 4; ++o) {
                    aB[sp][0][o] = f2fma(q0, d1[o], aB[sp][0][o]);
                    aB[sp][1][o] = f2fma(q1, d1[o], aB[sp][1][o]);
                }
                sp ^= 1;
                #pragma unroll
                for (int o = 0; o < 4; ++o) {
                    aB[sp][0][o] = f2fma(q0, d2[o], aB[sp][0][o]);
                    aB[sp][1][o] = f2fma(q1, d2[o], aB[sp][1][o]);
                }
            }
        }
        #pragma unroll
        for (int rp = 0; rp < 2; ++rp)
            #pragma unroll
            for (int o = 0; o < 4; ++o) {
                float2 A = unp(f2add(aA[0][rp][o], aA[1][rp][o]));
                float2 B = unp(f2add(aB[0][rp][o], aB[1][rp][o]));
                float zx = __fmul_rn(PW1S_C, __fadd_rn(A.x, __fmul_rn(INV3_C, B.x)));
                float zy = __fmul_rn(PW1S_C, __fadd_rn(A.y, __fmul_rn(INV3_C, B.y)));
                float hx = copysignf(sgp(fabsf(zx)), zx);
                float hy = copysignf(sgp(fabsf(zy)), zy);
                *(u64*)(hs1 + (wb + o) * RPC + rb + 2 * rp) = pk(hx, hy);
            }
    }

    // L1 vector (UNCHANGED)
    {
        const int rg = tid & 31, og = tid >> 5, rb = rg * 2;
        const float* Wb = g_W1v + og * 4;
        u64 acc[3][4] = {};
        for (int v = 0; v < V_IN; ++v) {
            u64 hv[3];
            #pragma unroll
            for (int k = 0; k < 3; ++k) hv[k] = *(const u64*)(hv0 + (v * 3 + k) * RPC + rb);
            #pragma unroll 4
            for (int u = 0; u < S_IN; ++u) {
                float4 w = __ldg((const float4*)(Wb + (u * V_IN + v) * V_H));
                DUP4(d, w);
                u64 hu = *(const u64*)(hs0 + u * RPC + rb);
                #pragma unroll
                for (int k = 0; k < 3; ++k) {
                    u64 p = f2mul(hu, hv[k]);
                    #pragma unroll
                    for (int o = 0; o < 4; ++o) acc[k][o] = f2fma(p, d[o], acc[k][o]);
                }
            }
        }
        #pragma unroll
        for (int wi = 0; wi < 4; ++wi) {
            int w = og * 4 + wi;
            float2 a0 = unp(acc[0][wi]), a1 = unp(acc[1][wi]), a2 = unp(acc[2][wi]);
            float nx = sqrtf(a0.x * a0.x + a1.x * a1.x + a2.x * a2.x);
            float ny = sqrtf(a0.y * a0.y + a1.y * a1.y + a2.y * a2.y);
            float mx = sgp(nx) / nx, my = sgp(ny) / ny;
            *(u64*)(hv1 + (w * 3 + 0) * RPC + rb) = pk(a0.x * mx, a0.y * my);
            *(u64*)(hv1 + (w * 3 + 1) * RPC + rb) = pk(a1.x * mx, a1.y * my);
            *(u64*)(hv1 + (w * 3 + 2) * RPC + rb) = pk(a2.x * mx, a2.y * my);
        }
    }
    __syncthreads();

    // L2 scalar — u-tiled by 4 (continuous gate, order-free)
    {
        const int rg = tid & 31, og = tid >> 5, rb = rg * 2;
        const float* Wb = g_W2s + og * 4;
        u64 acc[4] = {};
        for (int u0 = 0; u0 < S_H; u0 += 4) {
            u64 hu[4]; int fb[4];
            #pragma unroll
            for (int i = 0; i < 4; ++i) {
                int u = u0 + i;
                hu[i] = *(const u64*)(hs1 + u * RPC + rb);
                fb[i] = u * S_H - (u * (u - 1)) / 2 - u;
            }
            #pragma unroll
            for (int i = 0; i < 4; ++i)
                #pragma unroll
                for (int j = i; j < 4; ++j) {
                    float4 w = __ldg((const float4*)(Wb + (fb[i] + u0 + j) * S_OUT));
                    DUP4(d, w);
                    u64 p = f2mul(hu[i], hu[j]);
                    #pragma unroll
                    for (int o = 0; o < 4; ++o) acc[o] = f2fma(p, d[o], acc[o]);
                }
            #pragma unroll 2
            for (int v = u0 + 4; v < S_H; ++v) {
                u64 hv = *(const u64*)(hs1 + v * RPC + rb);
                #pragma unroll
                for (int i = 0; i < 4; ++i) {
                    float4 w = __ldg((const float4*)(Wb + (fb[i] + v) * S_OUT));
                    DUP4(d, w);
                    u64 p = f2mul(hu[i], hv);
                    #pragma unroll
                    for (int o = 0; o < 4; ++o) acc[o] = f2fma(p, d[o], acc[o]);
                }
            }
        }
        for (int u0 = 0; u0 < V_H; u0 += 4) {
            u64 h[4][3]; int fb[4];
            #pragma unroll
            for (int i = 0; i < 4; ++i) {
                int u = u0 + i;
                #pragma unroll
                for (int k = 0; k < 3; ++k)
                    h[i][k] = *(const u64*)(hv1 + (u * 3 + k) * RPC + rb);
                fb[i] = NF2_SS + u * V_H - (u * (u - 1)) / 2 - u;
            }
            #pragma unroll
            for (int i = 0; i < 4; ++i)
                #pragma unroll
                for (int j = i; j < 4; ++j) {
                    float4 w = __ldg((const float4*)(Wb + (fb[i] + u0 + j) * S_OUT));
                    DUP4(d, w);
                    u64 q = f2fma(h[i][2], h[j][2], f2fma(h[i][1], h[j][1], f2mul(h[i][0], h[j][0])));
                    #pragma unroll
                    for (int o = 0; o < 4; ++o) acc[o] = f2fma(q, d[o], acc[o]);
                }
            #pragma unroll 2
            for (int v = u0 + 4; v < V_H; ++v) {
                u64 g0 = *(const u64*)(hv1 + (v * 3 + 0) * RPC + rb);
                u64 g1 = *(const u64*)(hv1 + (v * 3 + 1) * RPC + rb);
                u64 g2 = *(const u64*)(hv1 + (v * 3 + 2) * RPC + rb);
                #pragma unroll
                for (int i = 0; i < 4; ++i) {
                    float4 w = __ldg((const float4*)(Wb + (fb[i] + v) * S_OUT));
                    DUP4(d, w);
                    u64 q = f2fma(h[i][2], g2, f2fma(h[i][1], g1, f2mul(h[i][0], g0)));
                    #pragma unroll
                    for (int o = 0; o < 4; ++o) acc[o] = f2fma(q, d[o], acc[o]);
                }
            }
        }
        int n0 = row0 + rb, n1 = n0 + 1;
        #pragma unroll
        for (int wi = 0; wi < 4; ++wi) {
            int w = og * 4 + wi;
            float bw = __ldg(b3 + w);
            float2 z = unp(acc[wi]);
            if (n0 < N) out[(size_t)n0 * 80 + w] = z.x * sgp(fabsf(z.x) + bw);
            if (n1 < N) out[(size_t)n1 * 80 + w] = z.y * sgp(fabsf(z.y) + bw);
        }
    }

    // L2 vector — v-tiled by 4 (continuous, order-free)
    {
        const int rg = tid & 31, og = tid >> 5, rb = rg * 2;
        const float2* Wb = g_W2v + og * 2;
        u64 acc[3][2] = {};
        for (int v0 = 0; v0 < V_H; v0 += 4) {
            u64 hv[4][3];
            #pragma unroll
            for (int j = 0; j < 4; ++j)
                #pragma unroll
                for (int k = 0; k < 3; ++k)
                    hv[j][k] = *(const u64*)(hv1 + ((v0 + j) * 3 + k) * RPC + rb);
            #pragma unroll 2
            for (int u = 0; u < S_H; ++u) {
                u64 hu = *(const u64*)(hs1 + u * RPC + rb);
                #pragma unroll
                for (int j = 0; j < 4; ++j) {
                    ulonglong2 wv = __ldg((const ulonglong2*)(Wb + (u * V_H + v0 + j) * V_OUT));
                    #pragma unroll
                    for (int k = 0; k < 3; ++k) {
                        u64 p = f2mul(hu, hv[j][k]);
                        acc[k][0] = f2fma(p, wv.x, acc[k][0]);
                        acc[k][1] = f2fma(p, wv.y, acc[k][1]);
                    }
                }
            }
        }
        int n0 = row0 + rb, n1 = n0 + 1;
        #pragma unroll
        for (int wi = 0; wi < 2; ++wi) {
            int w = og * 2 + wi;
            float bw = __ldg(b3 + 32 + w);
            float2 a0 = unp(acc[0][wi]), a1 = unp(acc[1][wi]), a2 = unp(acc[2][wi]);
            float mx = sgp(sqrtf(a0.x * a0.x + a1.x * a1.x + a2.x * a2.x) + bw);
            float my = sgp(sqrtf(a0.y * a0.y + a1.y * a1.y + a2.y * a2.y) + bw);
            if (n0 < N) {
                float* o = out + (size_t)n0 * 80 + 32 + 3 * w;
                o[0] = a0.x * mx; o[1] = a1.x * mx; o[2] = a2.x * mx;
            }
            if (n1 < N) {
                float* o = out + (size_t)n1 * 80 + 32 + 3 * w;
                o[0] = a0.y * my; o[1] = a1.y * my; o[2] = a2.y * my;
            }
        }
    }
}

extern "C" void kernel_launch(void* const* d_in, const int* in_sizes, int n_in,
                              void* d_out, int out_size) {
    const float* x     = (const float*)d_in[0];
    const float* Wsss1 = (const float*)d_in[1];
    const float* Wvvs1 = (const float*)d_in[2];
    const float* Wsvv1 = (const float*)d_in[3];
    const float* Wvsv1 = (const float*)d_in[4];
    const float* Wsss2 = (const float*)d_in[5];
    const float* Wvvs2 = (const float*)d_in[6];
    const float* Wsvv2 = (const float*)d_in[7];
    const float* Wvsv2 = (const float*)d_in[8];
    const float* b1    = (const float*)d_in[9];
    const float* b3    = (const float*)d_in[10];
    float* out = (float*)d_out;
    int N = in_sizes[0] / 80;

    prep_all<<<832, 256>>>(Wsvv1, Wvsv1, Wsss2, Wvvs2, Wsvv2, Wvsv2);

    const int smem = 240 * RPC * sizeof(float);  // 61440 B
    cudaFuncSetAttribute(dl_main, cudaFuncAttributeMaxDynamicSharedMemorySize, smem);
    int blocks = (N + RPC - 1) / RPC;
    dl_main<<<blocks, TPB, smem>>>(x, Wsss1, Wvvs1, b1, b3, out, N);
}

// round 17
// speedup vs baseline: 1.6149x; 1.1008x over previous
#include <cuda_runtime.h>
#include <math.h>

#define S_IN 32
#define V_IN 16
#define S_H  64
#define V_H  32
#define S_OUT 32
#define V_OUT 16
#define NF2_SS 2080
#define NF2    2608
#define RPC 64
#define TPB 256
#define PW1S_C  0.02795084971874737f
#define INV3_C  0.5773502691896258f
#define PW2S  0.0139754248593737f
#define PW2S3 0.0080687153045988f
#define CW1V  0.03125f
#define CW2V  0.015625f

typedef unsigned long long u64;

__device__ __align__(16) float  g_W1v[S_IN * V_IN * V_H];       // raw, scaled
__device__ __align__(16) float  g_W2s[NF2 * S_OUT];             // raw, folded+scaled
__device__ __align__(16) float4 g_W2v4[S_H * (V_H / 2) * 8];    // packed 2v x 2outs, scaled

__device__ __forceinline__ u64 f2mul(u64 a, u64 b) {
    u64 r; asm("mul.rn.f32x2 %0,%1,%2;" : "=l"(r) : "l"(a), "l"(b)); return r;
}
__device__ __forceinline__ u64 f2add(u64 a, u64 b) {
    u64 r; asm("add.rn.f32x2 %0,%1,%2;" : "=l"(r) : "l"(a), "l"(b)); return r;
}
__device__ __forceinline__ u64 f2fma(u64 a, u64 b, u64 c) {
    u64 r; asm("fma.rn.f32x2 %0,%1,%2,%3;" : "=l"(r) : "l"(a), "l"(b), "l"(c)); return r;
}
__device__ __forceinline__ float2 unp(u64 v) {
    return make_float2(__uint_as_float((unsigned)v), __uint_as_float((unsigned)(v >> 32)));
}
__device__ __forceinline__ u64 pk(float x, float y) {
    return (u64)__float_as_uint(x) | ((u64)__float_as_uint(y) << 32);
}
__device__ __forceinline__ u64 dupf(float w) {
    u64 b = (u64)__float_as_uint(w); return b | (b << 32);
}
// XLA logistic: 0.5 + 0.5*tanh(0.5*x)
__device__ __forceinline__ float sgp(float a) {
    float t = tanhf(__fmul_rn(a, 0.5f));
    return __fadd_rn(0.5f, __fmul_rn(0.5f, t));
}

#define DUP4(d, W_) u64 d[4] = {dupf((W_).x), dupf((W_).y), dupf((W_).z), dupf((W_).w)}

// ---- fused prep: 188416 items = 736 x 256 ----
__global__ void prep_all(const float* __restrict__ Wsvv1, const float* __restrict__ Wvsv1,
                         const float* __restrict__ Wsss2, const float* __restrict__ Wvvs2,
                         const float* __restrict__ Wsvv2, const float* __restrict__ Wvsv2)
{
    int i = blockIdx.x * blockDim.x + threadIdx.x;
    if (i < 16384) {                                  // w1v raw fused
        int w = i & 31, uv = i >> 5, u = uv >> 4, v = uv & 15;
        g_W1v[i] = CW1V * (Wsvv1[(u * V_IN + v) * V_H + w] + Wvsv1[(v * S_IN + u) * V_H + w]);
        return;
    }
    i -= 16384;
    if (i < 131072) {                                 // w2s ss folded raw
        int w = i & 31, uv = i >> 5, u = uv >> 6, v = uv & 63;
        if (v >= u) {
            int f = u * S_H - (u * (u - 1)) / 2 + (v - u);
            float val = Wsss2[(u * S_H + v) * S_OUT + w];
            if (v > u) val += Wsss2[(v * S_H + u) * S_OUT + w];
            g_W2s[f * S_OUT + w] = val * PW2S;
        }
        return;
    }
    i -= 131072;
    if (i < 32768) {                                  // w2s vv folded raw
        int w = i & 31, uv = i >> 5, u = uv >> 5, v = uv & 31;
        if (v >= u) {
            int f = NF2_SS + u * V_H - (u * (u - 1)) / 2 + (v - u);
            float val = Wvvs2[(u * V_H + v) * S_OUT + w];
            if (v > u) val += Wvvs2[(v * V_H + u) * S_OUT + w];
            g_W2s[f * S_OUT + w] = val * PW2S3;
        }
        return;
    }
    i -= 32768;
    if (i < 8192) {                                   // w2v packed 2v x 2outs
        int og = i & 7, t = i >> 3, p = t & 15, u = t >> 4;
        int v0 = p * 2, o0 = og * 2;
        g_W2v4[i] = make_float4(
            CW2V * (Wsvv2[(u * V_H + v0) * V_OUT + o0]     + Wvsv2[(v0 * S_H + u) * V_OUT + o0]),
            CW2V * (Wsvv2[(u * V_H + v0) * V_OUT + o0 + 1] + Wvsv2[(v0 * S_H + u) * V_OUT + o0 + 1]),
            CW2V * (Wsvv2[(u * V_H + v0 + 1) * V_OUT + o0]     + Wvsv2[((v0 + 1) * S_H + u) * V_OUT + o0]),
            CW2V * (Wsvv2[(u * V_H + v0 + 1) * V_OUT + o0 + 1] + Wvsv2[((v0 + 1) * S_H + u) * V_OUT + o0 + 1]));
    }
}

// ---- main fused kernel ----
__global__ void __launch_bounds__(TPB, 3)
dl_main(const float* __restrict__ x,
        const float* __restrict__ Wsss1, const float* __restrict__ Wvvs1,
        const float* __restrict__ b1, const float* __restrict__ b3,
        float* __restrict__ out, int N)
{
    extern __shared__ float sm[];
    float* hs0 = sm;                     // [32][RPC]  (reused as reduction buffer in L2s)
    float* hv0 = hs0 + S_IN * RPC;       // [48][RPC]
    float* hs1 = hv0 + 3 * V_IN * RPC;   // [64][RPC]
    float* hv1 = hs1 + S_H * RPC;        // [96][RPC]
    const int tid = threadIdx.x;
    const int row0 = blockIdx.x * RPC;

    // stage 0 (bit-exact)
    for (int idx = tid; idx < RPC * 48; idx += TPB) {
        int r = idx / 48, c = idx - r * 48, n = row0 + r;
        if (c < S_IN) {
            float v = (n < N) ? __ldg(x + (size_t)n * 80 + c) : 0.f;
            float m = sgp(__fadd_rn(fabsf(v), __ldg(b1 + c)));
            hs0[c * RPC + r] = __fmul_rn(v, m);
        } else {
            int u = c - S_IN;
            float a = 0.f, b = 0.f, d = 0.f;
            if (n < N) {
                const float* p = x + (size_t)n * 80 + 32 + 3 * u;
                a = __ldg(p); b = __ldg(p + 1); d = __ldg(p + 2);
            }
            float s2 = __fadd_rn(__fadd_rn(__fmul_rn(a, a), __fmul_rn(b, b)), __fmul_rn(d, d));
            float m = sgp(__fadd_rn(sqrtf(s2), __ldg(b1 + 32 + u)));
            hv0[(u * 3 + 0) * RPC + r] = __fmul_rn(a, m);
            hv0[(u * 3 + 1) * RPC + r] = __fmul_rn(b, m);
            hv0[(u * 3 + 2) * RPC + r] = __fmul_rn(d, m);
        }
    }
    __syncthreads();

    // L1 scalar EXACT path (UNCHANGED — flip-sensitive)
    {
        const int rg = tid & 15, og = tid >> 4, rb = rg * 4, wb = og * 4;
        u64 aA[2][2][4] = {}, aB[2][2][4] = {};
        for (int u = 0; u < S_IN; ++u) {
            ulonglong2 hu = *(const ulonglong2*)(hs0 + u * RPC + rb);
            {
                float4 w = __ldg((const float4*)(Wsss1 + (u * S_IN + u) * S_H + wb));
                DUP4(d, w);
                u64 p0 = f2mul(hu.x, hu.x), p1 = f2mul(hu.y, hu.y);
                int sp = u & 1;
                #pragma unroll
                for (int o = 0; o < 4; ++o) {
                    aA[sp][0][o] = f2fma(p0, d[o], aA[sp][0][o]);
                    aA[sp][1][o] = f2fma(p1, d[o], aA[sp][1][o]);
                }
            }
            #pragma unroll 2
            for (int v = u + 1; v < S_IN; ++v) {
                ulonglong2 hv = *(const ulonglong2*)(hs0 + v * RPC + rb);
                u64 p0 = f2mul(hu.x, hv.x), p1 = f2mul(hu.y, hv.y);
                float4 w1 = __ldg((const float4*)(Wsss1 + (u * S_IN + v) * S_H + wb));
                float4 w2 = __ldg((const float4*)(Wsss1 + (v * S_IN + u) * S_H + wb));
                DUP4(d1, w1); DUP4(d2, w2);
                int sp = v & 1;
                #pragma unroll
                for (int o = 0; o < 4; ++o) {
                    aA[sp][0][o] = f2fma(p0, d1[o], aA[sp][0][o]);
                    aA[sp][1][o] = f2fma(p1, d1[o], aA[sp][1][o]);
                }
                sp ^= 1;
                #pragma unroll
                for (int o = 0; o < 4; ++o) {
                    aA[sp][0][o] = f2fma(p0, d2[o], aA[sp][0][o]);
                    aA[sp][1][o] = f2fma(p1, d2[o], aA[sp][1][o]);
                }
            }
        }
        for (int u = 0; u < V_IN; ++u) {
            ulonglong2 h0 = *(const ulonglong2*)(hv0 + (u * 3 + 0) * RPC + rb);
            ulonglong2 h1 = *(const ulonglong2*)(hv0 + (u * 3 + 1) * RPC + rb);
            ulonglong2 h2 = *(const ulonglong2*)(hv0 + (u * 3 + 2) * RPC + rb);
            {
                float4 w = __ldg((const float4*)(Wvvs1 + (u * V_IN + u) * S_H + wb));
                DUP4(d, w);
                u64 q0 = f2fma(h2.x, h2.x, f2fma(h1.x, h1.x, f2mul(h0.x, h0.x)));
                u64 q1 = f2fma(h2.y, h2.y, f2fma(h1.y, h1.y, f2mul(h0.y, h0.y)));
                int sp = u & 1;
                #pragma unroll
                for (int o = 0; o < 4; ++o) {
                    aB[sp][0][o] = f2fma(q0, d[o], aB[sp][0][o]);
                    aB[sp][1][o] = f2fma(q1, d[o], aB[sp][1][o]);
                }
            }
            #pragma unroll 2
            for (int v = u + 1; v < V_IN; ++v) {
                ulonglong2 g0 = *(const ulonglong2*)(hv0 + (v * 3 + 0) * RPC + rb);
                ulonglong2 g1 = *(const ulonglong2*)(hv0 + (v * 3 + 1) * RPC + rb);
                ulonglong2 g2 = *(const ulonglong2*)(hv0 + (v * 3 + 2) * RPC + rb);
                u64 q0 = f2fma(h2.x, g2.x, f2fma(h1.x, g1.x, f2mul(h0.x, g0.x)));
                u64 q1 = f2fma(h2.y, g2.y, f2fma(h1.y, g1.y, f2mul(h0.y, g0.y)));
                float4 w1 = __ldg((const float4*)(Wvvs1 + (u * V_IN + v) * S_H + wb));
                float4 w2 = __ldg((const float4*)(Wvvs1 + (v * V_IN + u) * S_H + wb));
                DUP4(d1, w1); DUP4(d2, w2);
                int sp = v & 1;
                #pragma unroll
                for (int o = 0; o < 4; ++o) {
                    aB[sp][0][o] = f2fma(q0, d1[o], aB[sp][0][o]);
                    aB[sp][1][o] = f2fma(q1, d1[o], aB[sp][1][o]);
                }
                sp ^= 1;
                #pragma unroll
                for (int o = 0; o < 4; ++o) {
                    aB[sp][0][o] = f2fma(q0, d2[o], aB[sp][0][o]);
                    aB[sp][1][o] = f2fma(q1, d2[o], aB[sp][1][o]);
                }
            }
        }
        #pragma unroll
        for (int rp = 0; rp < 2; ++rp)
            #pragma unroll
            for (int o = 0; o < 4; ++o) {
                float2 A = unp(f2add(aA[0][rp][o], aA[1][rp][o]));
                float2 B = unp(f2add(aB[0][rp][o], aB[1][rp][o]));
                float zx = __fmul_rn(PW1S_C, __fadd_rn(A.x, __fmul_rn(INV3_C, B.x)));
                float zy = __fmul_rn(PW1S_C, __fadd_rn(A.y, __fmul_rn(INV3_C, B.y)));
                float hx = copysignf(sgp(fabsf(zx)), zx);
                float hy = copysignf(sgp(fabsf(zy)), zy);
                *(u64*)(hs1 + (wb + o) * RPC + rb + 2 * rp) = pk(hx, hy);
            }
    }

    // L1 vector (UNCHANGED)
    {
        const int rg = tid & 31, og = tid >> 5, rb = rg * 2;
        const float* Wb = g_W1v + og * 4;
        u64 acc[3][4] = {};
        for (int v = 0; v < V_IN; ++v) {
            u64 hv[3];
            #pragma unroll
            for (int k = 0; k < 3; ++k) hv[k] = *(const u64*)(hv0 + (v * 3 + k) * RPC + rb);
            #pragma unroll 4
            for (int u = 0; u < S_IN; ++u) {
                float4 w = __ldg((const float4*)(Wb + (u * V_IN + v) * V_H));
                DUP4(d, w);
                u64 hu = *(const u64*)(hs0 + u * RPC + rb);
                #pragma unroll
                for (int k = 0; k < 3; ++k) {
                    u64 p = f2mul(hu, hv[k]);
                    #pragma unroll
                    for (int o = 0; o < 4; ++o) acc[k][o] = f2fma(p, d[o], acc[k][o]);
                }
            }
        }
        #pragma unroll
        for (int wi = 0; wi < 4; ++wi) {
            int w = og * 4 + wi;
            float2 a0 = unp(acc[0][wi]), a1 = unp(acc[1][wi]), a2 = unp(acc[2][wi]);
            float nx = sqrtf(a0.x * a0.x + a1.x * a1.x + a2.x * a2.x);
            float ny = sqrtf(a0.y * a0.y + a1.y * a1.y + a2.y * a2.y);
            float mx = sgp(nx) / nx, my = sgp(ny) / ny;
            *(u64*)(hv1 + (w * 3 + 0) * RPC + rb) = pk(a0.x * mx, a0.y * my);
            *(u64*)(hv1 + (w * 3 + 1) * RPC + rb) = pk(a1.x * mx, a1.y * my);
            *(u64*)(hv1 + (w * 3 + 2) * RPC + rb) = pk(a2.x * mx, a2.y * my);
        }
    }
    __syncthreads();

    // L2 scalar — half-warp og (8 slices x 4 outs) x u-tile parity split across warp pairs
    {
        const int og = (tid >> 4) & 7;       // half-warp slice; lanes 0-15 / 16-31 share line
        const int uh = tid >> 7;             // warps 0-3 even tiles, warps 4-7 odd tiles
        const int rg = tid & 15, rb = rg * 4;
        const float* Wb = g_W2s + og * 4;
        u64 acc[2][4] = {};
        // ss tiles of 4 u's, parity-assigned
        for (int t = uh; t < 16; t += 2) {
            int u0 = t * 4;
            ulonglong2 hu[4]; int fb[4];
            #pragma unroll
            for (int i = 0; i < 4; ++i) {
                int u = u0 + i;
                hu[i] = *(const ulonglong2*)(hs1 + u * RPC + rb);
                fb[i] = u * S_H - (u * (u - 1)) / 2 - u;
            }
            #pragma unroll
            for (int i = 0; i < 4; ++i)
                #pragma unroll
                for (int j = i; j < 4; ++j) {
                    float4 w = __ldg((const float4*)(Wb + (fb[i] + u0 + j) * S_OUT));
                    DUP4(d, w);
                    u64 p0 = f2mul(hu[i].x, hu[j].x), p1 = f2mul(hu[i].y, hu[j].y);
                    #pragma unroll
                    for (int o = 0; o < 4; ++o) {
                        acc[0][o] = f2fma(p0, d[o], acc[0][o]);
                        acc[1][o] = f2fma(p1, d[o], acc[1][o]);
                    }
                }
            #pragma unroll 2
            for (int v = u0 + 4; v < S_H; ++v) {
                ulonglong2 hv = *(const ulonglong2*)(hs1 + v * RPC + rb);
                #pragma unroll
                for (int i = 0; i < 4; ++i) {
                    float4 w = __ldg((const float4*)(Wb + (fb[i] + v) * S_OUT));
                    DUP4(d, w);
                    u64 p0 = f2mul(hu[i].x, hv.x), p1 = f2mul(hu[i].y, hv.y);
                    #pragma unroll
                    for (int o = 0; o < 4; ++o) {
                        acc[0][o] = f2fma(p0, d[o], acc[0][o]);
                        acc[1][o] = f2fma(p1, d[o], acc[1][o]);
                    }
                }
            }
        }
        // vv tiles of 2 u's, parity-assigned
        for (int t = uh; t < 16; t += 2) {
            int u0 = t * 2;
            ulonglong2 h[2][3]; int fb[2];
            #pragma unroll
            for (int i = 0; i < 2; ++i) {
                int u = u0 + i;
                #pragma unroll
                for (int k = 0; k < 3; ++k)
                    h[i][k] = *(const ulonglong2*)(hv1 + (u * 3 + k) * RPC + rb);
                fb[i] = NF2_SS + u * V_H - (u * (u - 1)) / 2 - u;
            }
            #pragma unroll
            for (int i = 0; i < 2; ++i)
                #pragma unroll
                for (int j = i; j < 2; ++j) {
                    float4 w = __ldg((const float4*)(Wb + (fb[i] + u0 + j) * S_OUT));
                    DUP4(d, w);
                    u64 q0 = f2fma(h[i][2].x, h[j][2].x, f2fma(h[i][1].x, h[j][1].x, f2mul(h[i][0].x, h[j][0].x)));
                    u64 q1 = f2fma(h[i][2].y, h[j][2].y, f2fma(h[i][1].y, h[j][1].y, f2mul(h[i][0].y, h[j][0].y)));
                    #pragma unroll
                    for (int o = 0; o < 4; ++o) {
                        acc[0][o] = f2fma(q0, d[o], acc[0][o]);
                        acc[1][o] = f2fma(q1, d[o], acc[1][o]);
                    }
                }
            #pragma unroll 2
            for (int v = u0 + 2; v < V_H; ++v) {
                ulonglong2 g0 = *(const ulonglong2*)(hv1 + (v * 3 + 0) * RPC + rb);
                ulonglong2 g1 = *(const ulonglong2*)(hv1 + (v * 3 + 1) * RPC + rb);
                ulonglong2 g2 = *(const ulonglong2*)(hv1 + (v * 3 + 2) * RPC + rb);
                #pragma unroll
                for (int i = 0; i < 2; ++i) {
                    float4 w = __ldg((const float4*)(Wb + (fb[i] + v) * S_OUT));
                    DUP4(d, w);
                    u64 q0 = f2fma(h[i][2].x, g2.x, f2fma(h[i][1].x, g1.x, f2mul(h[i][0].x, g0.x)));
                    u64 q1 = f2fma(h[i][2].y, g2.y, f2fma(h[i][1].y, g1.y, f2mul(h[i][0].y, g0.y)));
                    #pragma unroll
                    for (int o = 0; o < 4; ++o) {
                        acc[0][o] = f2fma(q0, d[o], acc[0][o]);
                        acc[1][o] = f2fma(q1, d[o], acc[1][o]);
                    }
                }
            }
        }
        // cross-half reduction via smem (hs0 region is dead here)
        u64* red = (u64*)sm;
        if (uh == 1) {
            int base = (tid - 128) * 8;
            #pragma unroll
            for (int rp = 0; rp < 2; ++rp)
                #pragma unroll
                for (int o = 0; o < 4; ++o) red[base + rp * 4 + o] = acc[rp][o];
        }
        __syncthreads();
        if (uh == 0) {
            int base = tid * 8;
            #pragma unroll
            for (int rp = 0; rp < 2; ++rp) {
                int n0 = row0 + rb + 2 * rp, n1 = n0 + 1;
                #pragma unroll
                for (int o = 0; o < 4; ++o) {
                    u64 z2 = f2add(acc[rp][o], red[base + rp * 4 + o]);
                    int w = og * 4 + o;
                    float bw = __ldg(b3 + w);
                    float2 z = unp(z2);
                    if (n0 < N) out[(size_t)n0 * 80 + w] = z.x * sgp(fabsf(z.x) + bw);
                    if (n1 < N) out[(size_t)n1 * 80 + w] = z.y * sgp(fabsf(z.y) + bw);
                }
            }
        }
    }

    // L2 vector — v-tiled by 4, packed float4 weights (bit-identical chain)
    {
        const int rg = tid & 31, og = tid >> 5, rb = rg * 2;
        u64 acc[3][2] = {};
        for (int v0 = 0; v0 < V_H; v0 += 4) {
            const int p0 = v0 >> 1;
            u64 hv[4][3];
            #pragma unroll
            for (int j = 0; j < 4; ++j)
                #pragma unroll
                for (int k = 0; k < 3; ++k)
                    hv[j][k] = *(const u64*)(hv1 + ((v0 + j) * 3 + k) * RPC + rb);
            #pragma unroll 2
            for (int u = 0; u < S_H; ++u) {
                u64 hu = *(const u64*)(hs1 + u * RPC + rb);
                float4 A = __ldg(g_W2v4 + (u * 16 + p0) * 8 + og);
                float4 B = __ldg(g_W2v4 + (u * 16 + p0 + 1) * 8 + og);
                u64 wx[4] = {dupf(A.x), dupf(A.z), dupf(B.x), dupf(B.z)};
                u64 wy[4] = {dupf(A.y), dupf(A.w), dupf(B.y), dupf(B.w)};
                #pragma unroll
                for (int j = 0; j < 4; ++j) {
                    #pragma unroll
                    for (int k = 0; k < 3; ++k) {
                        u64 p = f2mul(hu, hv[j][k]);
                        acc[k][0] = f2fma(p, wx[j], acc[k][0]);
                        acc[k][1] = f2fma(p, wy[j], acc[k][1]);
                    }
                }
            }
        }
        int n0 = row0 + rb, n1 = n0 + 1;
        #pragma unroll
        for (int wi = 0; wi < 2; ++wi) {
            int w = og * 2 + wi;
            float bw = __ldg(b3 + 32 + w);
            float2 a0 = unp(acc[0][wi]), a1 = unp(acc[1][wi]), a2 = unp(acc[2][wi]);
            float mx = sgp(sqrtf(a0.x * a0.x + a1.x * a1.x + a2.x * a2.x) + bw);
            float my = sgp(sqrtf(a0.y * a0.y + a1.y * a1.y + a2.y * a2.y) + bw);
            if (n0 < N) {
                float* o = out + (size_t)n0 * 80 + 32 + 3 * w;
                o[0] = a0.x * mx; o[1] = a1.x * mx; o[2] = a2.x * mx;
            }
            if (n1 < N) {
                float* o = out + (size_t)n1 * 80 + 32 + 3 * w;
                o[0] = a0.y * my; o[1] = a1.y * my; o[2] = a2.y * my;
            }
        }
    }
}

extern "C" void kernel_launch(void* const* d_in, const int* in_sizes, int n_in,
                              void* d_out, int out_size) {
    const float* x     = (const float*)d_in[0];
    const float* Wsss1 = (const float*)d_in[1];
    const float* Wvvs1 = (const float*)d_in[2];
    const float* Wsvv1 = (const float*)d_in[3];
    const float* Wvsv1 = (const float*)d_in[4];
    const float* Wsss2 = (const float*)d_in[5];
    const float* Wvvs2 = (const float*)d_in[6];
    const float* Wsvv2 = (const float*)d_in[7];
    const float* Wvsv2 = (const float*)d_in[8];
    const float* b1    = (const float*)d_in[9];
    const float* b3    = (const float*)d_in[10];
    float* out = (float*)d_out;
    int N = in_sizes[0] / 80;

    prep_all<<<736, 256>>>(Wsvv1, Wvsv1, Wsss2, Wvvs2, Wsvv2, Wvsv2);

    const int smem = 240 * RPC * sizeof(float);  // 61440 B
    cudaFuncSetAttribute(dl_main, cudaFuncAttributeMaxDynamicSharedMemorySize, smem);
    int blocks = (N + RPC - 1) / RPC;
    dl_main<<<blocks, TPB, smem>>>(x, Wsss1, Wvvs1, b1, b3, out, N);
}